// round 9
// baseline (speedup 1.0000x reference)
#include <cuda_runtime.h>
#include <math.h>

// Problem constants
#define Bb 4
#define Ss 1024
#define Ee 1024
#define Hh 16
#define DH 64
#define MROWS (Bb * Ss)      // 4096
#define QKVN (3 * Ee)        // 3072
#define NROWS (Bb * Hh * Ss) // 65536 attention rows
#define NNZ_CAP 16

// Scratch
__device__ float g_qkv[(size_t)MROWS * QKVN];
__device__ float g_P[(size_t)Bb * Hh * Ss * Ss];
__device__ float g_ao[(size_t)MROWS * Ee];
__device__ float g_spill[(size_t)MROWS * Ee];
__device__ int   g_scnt[NROWS];
__device__ int   g_sidx[(size_t)NROWS * NNZ_CAP];
__device__ float g_sval[(size_t)NROWS * NNZ_CAP];

// ---------------------------------------------------------------------------
// Common helpers
// ---------------------------------------------------------------------------
__device__ __forceinline__ unsigned f2tf32_rna(float x) {
    unsigned u;
    asm("cvt.rna.tf32.f32 %0, %1;" : "=r"(u) : "f"(x));
    return u;
}

template <int PASSES>
__device__ __forceinline__ void splitP(float x, unsigned& h, unsigned& l) {
    if (PASSES == 1) {
        h = f2tf32_rna(x);
        l = 0u;
    } else {
        unsigned hu = __float_as_uint(x) & 0xffffe000u;  // truncate
        h = hu;
        l = __float_as_uint(x - __uint_as_float(hu));    // residual
    }
}
__device__ __forceinline__ void split32(float x, unsigned& h, unsigned& l) {
    unsigned hu = __float_as_uint(x) & 0xffffe000u;
    h = hu;
    l = __float_as_uint(x - __uint_as_float(hu));
}

#define MMA_TF32(cc, aa, bb)                                              \
    asm volatile(                                                          \
        "mma.sync.aligned.m16n8k8.row.col.f32.tf32.tf32.f32 "             \
        "{%0,%1,%2,%3}, {%4,%5,%6,%7}, {%8,%9}, {%0,%1,%2,%3};"           \
        : "+f"(cc[0]), "+f"(cc[1]), "+f"(cc[2]), "+f"(cc[3])              \
        : "r"(aa[0]), "r"(aa[1]), "r"(aa[2]), "r"(aa[3]),                 \
          "r"(bb[0]), "r"(bb[1]))

#define CP_ASYNC16(dst, src)                                              \
    asm volatile("cp.async.cg.shared.global [%0], [%1], 16;"              \
                 :: "r"(dst), "l"(src))
#define CP_COMMIT() asm volatile("cp.async.commit_group;")
#define CP_WAIT_ALL() asm volatile("cp.async.wait_group 0;")
#define CP_WAIT1() asm volatile("cp.async.wait_group 1;")

// ===========================================================================
// G1: 128x128 CTA tile, BK=32, 128 threads (4 warps 2x2, warp tile 64x64).
//   3-stage cp.async pipeline. PASSES: 3/2/1 tf32 correction passes.
// ===========================================================================
#define ASTR 36
#define G1_A_TILE (128 * ASTR)
#define G1_BN_TILE (32 * 128)
#define G1_SMEM_N (3 * (G1_A_TILE + G1_BN_TILE))   // 104448 B

__device__ __forceinline__ void g1_load(
    const float* __restrict__ Abase, const float* __restrict__ Bbase,
    int lda, int ldb, int k0, float* As, float* Bs, int tid)
{
    {
        const int row = tid >> 3;
        const int col = (tid & 7) * 4;
        const float* src = Abase + (size_t)row * lda + k0 + col;
        unsigned dst = (unsigned)__cvta_generic_to_shared(As + row * ASTR + col);
        #pragma unroll
        for (int r = 0; r < 8; ++r)
            CP_ASYNC16(dst + r * 16 * ASTR * 4, src + (size_t)r * 16 * lda);
    }
    #pragma unroll
    for (int r = 0; r < 8; ++r) {
        const int elem = r * 128 + tid;
        const int kr = elem >> 5;
        const int c4 = (elem & 31) * 4;
        const float* src = Bbase + (size_t)(k0 + kr) * ldb + c4;
        unsigned dst = (unsigned)__cvta_generic_to_shared(
            Bs + kr * 128 + (c4 ^ (8 * (kr & 3))));
        CP_ASYNC16(dst, src);
    }
}

template <int PASSES>
__global__ __launch_bounds__(128) void gemm_g1_kernel(
    const float* __restrict__ A, const float* __restrict__ B,
    const float* __restrict__ bias, float* __restrict__ C,
    int K, int lda, int ldb, int ldc, float alpha)
{
    extern __shared__ float sm[];
    float* As = sm;
    float* Bs = sm + 3 * G1_A_TILE;

    const int tid = threadIdx.x;
    const float* Abase = A + (size_t)blockIdx.y * 128 * lda;
    const float* Bbase = B + blockIdx.x * 128;
    float* Cb = C;

    const int warp = tid >> 5, lane = tid & 31;
    const int wm = warp >> 1, wn = warp & 1;
    const int g = lane >> 2, t = lane & 3;

    float acc[4][8][4];
    #pragma unroll
    for (int mt = 0; mt < 4; ++mt)
        #pragma unroll
        for (int nt = 0; nt < 8; ++nt)
            #pragma unroll
            for (int r = 0; r < 4; ++r) acc[mt][nt][r] = 0.f;

    const int KT = K >> 5;

    g1_load(Abase, Bbase, lda, ldb, 0, As, Bs, tid);
    CP_COMMIT();
    if (KT > 1) {
        g1_load(Abase, Bbase, lda, ldb, 32, As + G1_A_TILE, Bs + G1_BN_TILE, tid);
        CP_COMMIT();
    }

    for (int kt = 0; kt < KT; ++kt) {
        if (kt < KT - 1) CP_WAIT1(); else CP_WAIT_ALL();
        __syncthreads();

        if (kt + 2 < KT) {
            const int buf = (kt + 2) % 3;
            g1_load(Abase, Bbase, lda, ldb, (kt + 2) * 32,
                    As + buf * G1_A_TILE, Bs + buf * G1_BN_TILE, tid);
            CP_COMMIT();
        }

        const float* Ac = As + (kt % 3) * G1_A_TILE;
        const float* Bc = Bs + (kt % 3) * G1_BN_TILE;

        #pragma unroll
        for (int kk = 0; kk < 32; kk += 8) {
            unsigned a_h[4][4], a_l[4][4];
            const int kcol = kk + t;
            #pragma unroll
            for (int mt = 0; mt < 4; ++mt) {
                const int m0 = wm * 64 + mt * 16 + g;
                splitP<PASSES>(Ac[m0 * ASTR + kcol],           a_h[mt][0], a_l[mt][0]);
                splitP<PASSES>(Ac[(m0 + 8) * ASTR + kcol],     a_h[mt][1], a_l[mt][1]);
                splitP<PASSES>(Ac[m0 * ASTR + kcol + 4],       a_h[mt][2], a_l[mt][2]);
                splitP<PASSES>(Ac[(m0 + 8) * ASTR + kcol + 4], a_h[mt][3], a_l[mt][3]);
            }
            #pragma unroll
            for (int nt = 0; nt < 8; ++nt) {
                const int n0 = wn * 64 + nt * 8 + g;
                const int nsw = n0 ^ (8 * t);
                float y0 = Bc[(kk + t) * 128 + nsw];
                float y1 = Bc[(kk + t + 4) * 128 + nsw];
                unsigned b_h[2], b_l[2];
                splitP<PASSES>(y0, b_h[0], b_l[0]);
                splitP<PASSES>(y1, b_h[1], b_l[1]);
                #pragma unroll
                for (int mt = 0; mt < 4; ++mt) {
                    MMA_TF32(acc[mt][nt], a_h[mt], b_h);
                    if (PASSES >= 2) MMA_TF32(acc[mt][nt], a_h[mt], b_l);
                    if (PASSES >= 3) MMA_TF32(acc[mt][nt], a_l[mt], b_h);
                }
            }
        }
    }

    #pragma unroll
    for (int mt = 0; mt < 4; ++mt) {
        #pragma unroll
        for (int nt = 0; nt < 8; ++nt) {
            const int row0 = blockIdx.y * 128 + wm * 64 + mt * 16 + g;
            const int col  = blockIdx.x * 128 + wn * 64 + nt * 8 + t * 2;
            float bv0 = 0.f, bv1 = 0.f;
            if (bias) { bv0 = bias[col]; bv1 = bias[col + 1]; }
            float2 v0 = make_float2(acc[mt][nt][0] * alpha + bv0,
                                    acc[mt][nt][1] * alpha + bv1);
            *(float2*)(Cb + (size_t)row0 * ldc + col) = v0;
            float2 v1 = make_float2(acc[mt][nt][2] * alpha + bv0,
                                    acc[mt][nt][3] * alpha + bv1);
            *(float2*)(Cb + (size_t)(row0 + 8) * ldc + col) = v1;
        }
    }
}

// ===========================================================================
// Fused QK^T + softmax + threshold mask + renorm + sparse extraction.
//   CTA = (32 q-rows, one bh). 256 threads (8 warps).
//   Phase 1: logits 32x1024 via tf32x3 MMA; K streamed in 16x64-row chunks
//            through a 3-buffer cp.async pipeline (chunk c+2 issued at iter c;
//            wait_group 1 guarantees chunk c complete — proven G1 schedule).
//   Phase 2: per-warp row softmax + mask; filtered P to gmem; ballot nnz.
// ===========================================================================
#define QKS 68                      // Q/K smem row stride (64 + 4 pad)
#define LSS 1032                    // logits smem row stride
#define FQ_QS (32 * QKS)            // 2176 floats
#define FQ_KS (64 * QKS)            // 4352 floats per buffer
#define FQ_SMEM_BYTES ((FQ_QS + 3 * FQ_KS + 32 * LSS) * 4)   // 193,024 B

__device__ __forceinline__ void fq_load_k(
    const float* __restrict__ Kbase, int chunk, float* Ks, int tid)
{
    const int row = tid >> 2;                 // 0..63
    const int s = tid & 3;
    const float* src = Kbase + (size_t)(chunk * 64 + row) * QKVN + s * 4;
    unsigned dst = (unsigned)__cvta_generic_to_shared(Ks + row * QKS + s * 4);
    #pragma unroll
    for (int i = 0; i < 4; ++i)
        CP_ASYNC16(dst + i * 64, src + i * 16);
}

__global__ __launch_bounds__(256) void qk_softmax_kernel(
    const float* __restrict__ qkv, float* __restrict__ P,
    int* __restrict__ scnt, int* __restrict__ sidx, float* __restrict__ sval,
    int writeP)
{
    extern __shared__ float sm[];
    float* Qs = sm;                        // [32][QKS]
    float* Ks = sm + FQ_QS;                // 3 x [64][QKS]
    float* Ls = sm + FQ_QS + 3 * FQ_KS;    // [32][LSS]

    const int tid = threadIdx.x;
    const int warp = tid >> 5, lane = tid & 31;
    const int g = lane >> 2, t = lane & 3;

    const int i0 = blockIdx.x * 32;
    const int z = blockIdx.y;
    const int b = z >> 4, h = z & 15;

    const float* Qg = qkv + (size_t)b * Ss * QKVN + h * DH;
    const float* Kg = qkv + (size_t)b * Ss * QKVN + Ee + h * DH;

    // ---- prologue: G0 = {Q tile, K chunk 0}, G1 = {K chunk 1} ----
    {
        const int row = tid >> 3;          // 0..31
        const int s = tid & 7;
        const float* src = Qg + (size_t)(i0 + row) * QKVN + s * 4;
        unsigned dst = (unsigned)__cvta_generic_to_shared(Qs + row * QKS + s * 4);
        CP_ASYNC16(dst, src);
        CP_ASYNC16(dst + 128, src + 32);
    }
    fq_load_k(Kg, 0, Ks, tid);
    CP_COMMIT();
    fq_load_k(Kg, 1, Ks + FQ_KS, tid);
    CP_COMMIT();

    unsigned ah[2][8][4], al[2][8][4];     // Q fragments, loaded once

    // ---- phase 1: 16 chunks of 64 K-rows, 3-stage pipeline ----
    for (int c = 0; c < 16; ++c) {
        if (c < 15) CP_WAIT1(); else CP_WAIT_ALL();   // chunk c complete
        __syncthreads();

        if (c == 0) {
            #pragma unroll
            for (int mt = 0; mt < 2; ++mt)
                #pragma unroll
                for (int ks = 0; ks < 8; ++ks) {
                    const int m0 = mt * 16 + g;
                    const int kc = ks * 8 + t;
                    split32(Qs[m0 * QKS + kc],           ah[mt][ks][0], al[mt][ks][0]);
                    split32(Qs[(m0 + 8) * QKS + kc],     ah[mt][ks][1], al[mt][ks][1]);
                    split32(Qs[m0 * QKS + kc + 4],       ah[mt][ks][2], al[mt][ks][2]);
                    split32(Qs[(m0 + 8) * QKS + kc + 4], ah[mt][ks][3], al[mt][ks][3]);
                }
        }
        if (c + 2 < 16) {                  // issue chunk c+2 into buffer (c+2)%3
            fq_load_k(Kg, c + 2, Ks + ((c + 2) % 3) * FQ_KS, tid);
            CP_COMMIT();
        }

        const float* Kc = Ks + (c % 3) * FQ_KS;
        float acc[2][4] = {};

        const int n0 = warp * 8 + g;       // K-row within chunk
        #pragma unroll
        for (int ks = 0; ks < 8; ++ks) {
            float y0 = Kc[n0 * QKS + ks * 8 + t];
            float y1 = Kc[n0 * QKS + ks * 8 + t + 4];
            unsigned bh2[2], bl2[2];
            split32(y0, bh2[0], bl2[0]);
            split32(y1, bh2[1], bl2[1]);
            #pragma unroll
            for (int mt = 0; mt < 2; ++mt) {
                MMA_TF32(acc[mt], ah[mt][ks], bh2);
                MMA_TF32(acc[mt], ah[mt][ks], bl2);
                MMA_TF32(acc[mt], al[mt][ks], bh2);
            }
        }

        const int cb = c * 64 + warp * 8 + 2 * t;
        #pragma unroll
        for (int mt = 0; mt < 2; ++mt) {
            const int r0 = mt * 16 + g;
            *(float2*)(Ls + r0 * LSS + cb) =
                make_float2(acc[mt][0] * 0.125f, acc[mt][1] * 0.125f);
            *(float2*)(Ls + (r0 + 8) * LSS + cb) =
                make_float2(acc[mt][2] * 0.125f, acc[mt][3] * 0.125f);
        }
    }
    __syncthreads();

    // ---- phase 2: softmax + mask, 4 rows per warp ----
    for (int rr = 0; rr < 4; ++rr) {
        const int row = warp * 4 + rr;
        float* L = Ls + row * LSS;
        const int grow = z * Ss + i0 + row;
        float* Pr = P + (size_t)z * Ss * Ss + (size_t)(i0 + row) * Ss;

        // max + argmax (first occurrence)
        float m = -3.4e38f; int mi = 0x7fffffff;
        #pragma unroll 8
        for (int it = 0; it < 32; ++it) {
            const int col = it * 32 + lane;
            float v = L[col];
            if (v > m) { m = v; mi = col; }
        }
        #pragma unroll
        for (int o = 16; o > 0; o >>= 1) {
            float ov = __shfl_xor_sync(0xffffffffu, m, o);
            int   oi = __shfl_xor_sync(0xffffffffu, mi, o);
            if (ov > m || (ov == m && oi < mi)) { m = ov; mi = oi; }
        }

        // exp + Z (store e back into smem)
        float zs = 0.f;
        #pragma unroll 8
        for (int it = 0; it < 32; ++it) {
            const int col = it * 32 + lane;
            float e = expf(L[col] - m);
            L[col] = e;
            zs += e;
        }
        #pragma unroll
        for (int o = 16; o > 0; o >>= 1) zs += __shfl_xor_sync(0xffffffffu, zs, o);
        const float invZ = 1.0f / zs;

        // masked sum
        float ms = 0.f;
        #pragma unroll 8
        for (int it = 0; it < 32; ++it) {
            float p = L[it * 32 + lane] * invZ;
            if (p > 0.1f) ms += p;
        }
        #pragma unroll
        for (int o = 16; o > 0; o >>= 1) ms += __shfl_xor_sync(0xffffffffu, ms, o);

        int cnt = 0;
        if (ms > 0.f) {
            const float inv = 1.0f / ms;
            #pragma unroll 8
            for (int it = 0; it < 32; ++it) {
                const int col = it * 32 + lane;
                float p = L[col] * invZ;
                const bool sel = p > 0.1f;
                float q = sel ? p * inv : 0.f;
                if (writeP) Pr[col] = q;
                unsigned msk = __ballot_sync(0xffffffffu, sel);
                if (sel) {
                    int pos = cnt + __popc(msk & ((1u << lane) - 1u));
                    if (pos < NNZ_CAP) {
                        sidx[(size_t)grow * NNZ_CAP + pos] = col;
                        sval[(size_t)grow * NNZ_CAP + pos] = q;
                    }
                }
                cnt += __popc(msk);
            }
        } else {
            if (writeP) {
                #pragma unroll 8
                for (int it = 0; it < 32; ++it) {
                    const int col = it * 32 + lane;
                    Pr[col] = (col == mi) ? 1.f : 0.f;
                }
            }
            if (lane == (mi & 31)) {
                sidx[(size_t)grow * NNZ_CAP] = mi;
                sval[(size_t)grow * NNZ_CAP] = 1.0f;
            }
            cnt = 1;
        }
        if (lane == 0) scnt[grow] = (cnt < NNZ_CAP) ? cnt : NNZ_CAP;
    }
}

// ---------------------------------------------------------------------------
// Sparse AV: one warp per attention row. out[i,:] = sum_k val_k * V[idx_k,:]
// ---------------------------------------------------------------------------
__global__ __launch_bounds__(256) void av_sparse_kernel(
    const int* __restrict__ scnt, const int* __restrict__ sidx,
    const float* __restrict__ sval, const float* __restrict__ qkv,
    float* __restrict__ ao)
{
    const int r = blockIdx.x * 8 + (threadIdx.x >> 5);
    const int lane = threadIdx.x & 31;

    const int bh = r >> 10, i = r & 1023;
    const int b = bh >> 4, h = bh & 15;
    const float* Vb = qkv + (size_t)b * Ss * QKVN + 2 * Ee + h * DH;

    const int c = scnt[r];
    float a0 = 0.f, a1 = 0.f;
    for (int k = 0; k < c; ++k) {
        const int j = sidx[(size_t)r * NNZ_CAP + k];
        const float v = sval[(size_t)r * NNZ_CAP + k];
        const float* Vr = Vb + (size_t)j * QKVN;
        a0 += v * Vr[lane];
        a1 += v * Vr[lane + 32];
    }
    float* Or = ao + (size_t)(b * Ss + i) * Ee + h * DH;
    Or[lane] = a0;
    Or[lane + 32] = a1;
}

// ---------------------------------------------------------------------------
// Launch
// ---------------------------------------------------------------------------
static float* sym_addr(const void* sym)
{
    void* p = nullptr;
    cudaGetSymbolAddress(&p, sym);
    return (float*)p;
}

extern "C" void kernel_launch(void* const* d_in, const int* in_sizes, int n_in,
                              void* d_out, int out_size)
{
    const float* x      = (const float*)d_in[0];
    const float* w_qkv  = (const float*)d_in[1];
    const float* b_qkv  = (const float*)d_in[2];
    const float* w_proj = (const float*)d_in[3];
    const float* b_proj = (const float*)d_in[4];

    float* qkv = sym_addr(g_qkv);
    float* ao  = sym_addr(g_ao);
    int*   scnt = (int*)sym_addr(g_scnt);
    int*   sidx = (int*)sym_addr(g_sidx);
    float* sval = sym_addr(g_sval);

    const size_t OUT_N  = (size_t)Bb * Ss * Ee;
    const size_t ATTN_N = (size_t)Bb * Hh * Ss * Ss;

    float* out = (float*)d_out;
    float* P;
    float* mainOut;
    int writeP = 1;
    if ((size_t)out_size >= OUT_N + ATTN_N) {
        mainOut = out;
        P = out + OUT_N;
    } else if ((size_t)out_size == ATTN_N) {
        mainOut = sym_addr(g_spill);
        P = out;
    } else {
        mainOut = out;
        P = sym_addr(g_P);
        writeP = 0;                       // attn not observed; skip the 268MB write
    }

    const int smemN = G1_SMEM_N * sizeof(float);   // 104448
    cudaFuncSetAttribute(gemm_g1_kernel<3>,
                         cudaFuncAttributeMaxDynamicSharedMemorySize, smemN);
    cudaFuncSetAttribute(gemm_g1_kernel<2>,
                         cudaFuncAttributeMaxDynamicSharedMemorySize, smemN);
    cudaFuncSetAttribute(gemm_g1_kernel<1>,
                         cudaFuncAttributeMaxDynamicSharedMemorySize, smemN);
    cudaFuncSetAttribute(qk_softmax_kernel,
                         cudaFuncAttributeMaxDynamicSharedMemorySize, FQ_SMEM_BYTES);

    // 1a. Q,K projection: [4096,1024] @ [1024,2048] + bias  (tf32x3 — feeds mask)
    {
        dim3 grid(2048 / 128, MROWS / 128, 1);
        gemm_g1_kernel<3><<<grid, 128, smemN>>>(
            x, w_qkv, b_qkv, qkv, Ee, Ee, QKVN, QKVN, 1.0f);
    }
    // 1b. V projection: [4096,1024] @ [1024,1024] + bias  (tf32x1 — output only)
    {
        dim3 grid(1024 / 128, MROWS / 128, 1);
        gemm_g1_kernel<1><<<grid, 128, smemN>>>(
            x, w_qkv + 2048, b_qkv + 2048, qkv + 2048, Ee, Ee, QKVN, QKVN, 1.0f);
    }
    // 2. fused QK^T + softmax + mask + sparse extraction
    {
        dim3 grid(Ss / 32, Bb * Hh, 1);
        qk_softmax_kernel<<<grid, 256, FQ_SMEM_BYTES>>>(
            qkv, P, scnt, sidx, sval, writeP);
    }
    // 3. sparse AV (<= 9 nnz per row guaranteed)
    av_sparse_kernel<<<NROWS / 8, 256>>>(scnt, sidx, sval, qkv, ao);
    // 4. output projection: [4096,1024] @ [1024,1024] + bias  (tf32x2)
    {
        dim3 grid(Ee / 128, MROWS / 128, 1);
        gemm_g1_kernel<2><<<grid, 128, smemN>>>(
            ao, w_proj, b_proj, mainOut, Ee, Ee, Ee, Ee, 1.0f);
    }
}

// round 10
// speedup vs baseline: 1.1122x; 1.1122x over previous
#include <cuda_runtime.h>
#include <math.h>

// Problem constants
#define Bb 4
#define Ss 1024
#define Ee 1024
#define Hh 16
#define DH 64
#define MROWS (Bb * Ss)      // 4096
#define QKVN (3 * Ee)        // 3072
#define NROWS (Bb * Hh * Ss) // 65536 attention rows
#define NNZ_CAP 16

// Scratch
__device__ float g_qkv[(size_t)MROWS * QKVN];
__device__ float g_P[(size_t)Bb * Hh * Ss * Ss];
__device__ float g_ao[(size_t)MROWS * Ee];
__device__ float g_spill[(size_t)MROWS * Ee];
__device__ int   g_scnt[NROWS];
__device__ int   g_sidx[(size_t)NROWS * NNZ_CAP];
__device__ float g_sval[(size_t)NROWS * NNZ_CAP];

// ---------------------------------------------------------------------------
// Common helpers
// ---------------------------------------------------------------------------
__device__ __forceinline__ unsigned f2tf32_rna(float x) {
    unsigned u;
    asm("cvt.rna.tf32.f32 %0, %1;" : "=r"(u) : "f"(x));
    return u;
}

template <int PASSES>
__device__ __forceinline__ void splitP(float x, unsigned& h, unsigned& l) {
    if (PASSES == 1) {
        h = f2tf32_rna(x);            // single pass: round-to-nearest tf32
        l = 0u;
    } else {
        unsigned hu = __float_as_uint(x) & 0xffffe000u;  // truncate
        h = hu;
        l = __float_as_uint(x - __uint_as_float(hu));    // residual
    }
}

#define MMA_TF32(cc, aa, bb)                                              \
    asm volatile(                                                          \
        "mma.sync.aligned.m16n8k8.row.col.f32.tf32.tf32.f32 "             \
        "{%0,%1,%2,%3}, {%4,%5,%6,%7}, {%8,%9}, {%0,%1,%2,%3};"           \
        : "+f"(cc[0]), "+f"(cc[1]), "+f"(cc[2]), "+f"(cc[3])              \
        : "r"(aa[0]), "r"(aa[1]), "r"(aa[2]), "r"(aa[3]),                 \
          "r"(bb[0]), "r"(bb[1]))

#define CP_ASYNC16(dst, src)                                              \
    asm volatile("cp.async.cg.shared.global [%0], [%1], 16;"              \
                 :: "r"(dst), "l"(src))
#define CP_COMMIT() asm volatile("cp.async.commit_group;")
#define CP_WAIT_ALL() asm volatile("cp.async.wait_group 0;")
#define CP_WAIT1() asm volatile("cp.async.wait_group 1;")

// ===========================================================================
// G1: 128x128 CTA tile, BK=32, 128 threads (4 warps as 2x2, warp tile 64x64).
//   3-stage cp.async pipeline, single __syncthreads per K-iter.
//   PASSES: 3 = full tf32x3 (fp32-accurate), 2 = hi*hi+hi*lo, 1 = plain tf32.
// MODE: 0 = plain (C=alpha*A@B(+bias)),  1 = QK^T per (b,h)
// ===========================================================================
#define ASTR 36
#define G1_A_TILE (128 * ASTR)        // 4608 floats
#define G1_BT_TILE (128 * ASTR)       // 4608
#define G1_BN_TILE (32 * 128)         // 4096
#define G1_SMEM_T (3 * (G1_A_TILE + G1_BT_TILE))   // 110592 B
#define G1_SMEM_N (3 * (G1_A_TILE + G1_BN_TILE))   // 104448 B

template <int TRANSB>
__device__ __forceinline__ void g1_load(
    const float* __restrict__ Abase, const float* __restrict__ Bbase,
    int lda, int ldb, int k0, float* As, float* Bs, int tid)
{
    // A: 128 x 32  (128 threads -> 8 x float4 each)
    {
        const int row = tid >> 3;               // 0..15
        const int col = (tid & 7) * 4;
        const float* src = Abase + (size_t)row * lda + k0 + col;
        unsigned dst = (unsigned)__cvta_generic_to_shared(As + row * ASTR + col);
        #pragma unroll
        for (int r = 0; r < 8; ++r)
            CP_ASYNC16(dst + r * 16 * ASTR * 4, src + (size_t)r * 16 * lda);
    }
    if (TRANSB) {
        const int row = tid >> 3;
        const int col = (tid & 7) * 4;
        const float* src = Bbase + (size_t)row * ldb + k0 + col;
        unsigned dst = (unsigned)__cvta_generic_to_shared(Bs + row * ASTR + col);
        #pragma unroll
        for (int r = 0; r < 8; ++r)
            CP_ASYNC16(dst + r * 16 * ASTR * 4, src + (size_t)r * 16 * ldb);
    } else {
        #pragma unroll
        for (int r = 0; r < 8; ++r) {
            const int elem = r * 128 + tid;
            const int kr = elem >> 5;
            const int c4 = (elem & 31) * 4;
            const float* src = Bbase + (size_t)(k0 + kr) * ldb + c4;
            unsigned dst = (unsigned)__cvta_generic_to_shared(
                Bs + kr * 128 + (c4 ^ (8 * (kr & 3))));
            CP_ASYNC16(dst, src);
        }
    }
}

template <int MODE, int TRANSB, int PASSES>
__global__ __launch_bounds__(128) void gemm_g1_kernel(
    const float* __restrict__ A, const float* __restrict__ B,
    const float* __restrict__ bias, float* __restrict__ C,
    int K, int lda, int ldb, int ldc, float alpha)
{
    extern __shared__ float sm[];
    const int B_TILE = TRANSB ? G1_BT_TILE : G1_BN_TILE;
    float* As = sm;                         // 3 stages
    float* Bs = sm + 3 * G1_A_TILE;         // 3 stages

    const int tid = threadIdx.x;
    const int z = blockIdx.z;

    const float* Ab;
    const float* Bbp;
    float* Cb;
    if (MODE == 0) {
        Ab = A; Bbp = B; Cb = C;
    } else {                              // QK^T per (b,h)
        const int b = z >> 4, h = z & 15;
        Ab  = A + (size_t)b * Ss * QKVN + h * DH;
        Bbp = B + (size_t)b * Ss * QKVN + Ee + h * DH;
        Cb  = C + (size_t)z * Ss * Ss;
    }

    const float* Abase = Ab + (size_t)blockIdx.y * 128 * lda;
    const float* Bbase = TRANSB ? (Bbp + (size_t)blockIdx.x * 128 * ldb)
                                : (Bbp + blockIdx.x * 128);

    const int warp = tid >> 5, lane = tid & 31;
    const int wm = warp >> 1, wn = warp & 1;      // 2x2 warps, warp tile 64x64
    const int g = lane >> 2, t = lane & 3;

    float acc[4][8][4];
    #pragma unroll
    for (int mt = 0; mt < 4; ++mt)
        #pragma unroll
        for (int nt = 0; nt < 8; ++nt)
            #pragma unroll
            for (int r = 0; r < 4; ++r) acc[mt][nt][r] = 0.f;

    const int KT = K >> 5;

    g1_load<TRANSB>(Abase, Bbase, lda, ldb, 0, As, Bs, tid);
    CP_COMMIT();
    if (KT > 1) {
        g1_load<TRANSB>(Abase, Bbase, lda, ldb, 32,
                        As + G1_A_TILE, Bs + B_TILE, tid);
        CP_COMMIT();
    }

    for (int kt = 0; kt < KT; ++kt) {
        if (kt < KT - 1) CP_WAIT1(); else CP_WAIT_ALL();
        __syncthreads();

        if (kt + 2 < KT) {
            const int buf = (kt + 2) % 3;
            g1_load<TRANSB>(Abase, Bbase, lda, ldb, (kt + 2) * 32,
                            As + buf * G1_A_TILE, Bs + buf * B_TILE, tid);
            CP_COMMIT();
        }

        const float* Ac = As + (kt % 3) * G1_A_TILE;
        const float* Bc = Bs + (kt % 3) * B_TILE;

        #pragma unroll
        for (int kk = 0; kk < 32; kk += 8) {
            unsigned a_h[4][4], a_l[4][4];
            const int kcol = kk + t;
            #pragma unroll
            for (int mt = 0; mt < 4; ++mt) {
                const int m0 = wm * 64 + mt * 16 + g;
                splitP<PASSES>(Ac[m0 * ASTR + kcol],           a_h[mt][0], a_l[mt][0]);
                splitP<PASSES>(Ac[(m0 + 8) * ASTR + kcol],     a_h[mt][1], a_l[mt][1]);
                splitP<PASSES>(Ac[m0 * ASTR + kcol + 4],       a_h[mt][2], a_l[mt][2]);
                splitP<PASSES>(Ac[(m0 + 8) * ASTR + kcol + 4], a_h[mt][3], a_l[mt][3]);
            }
            #pragma unroll
            for (int nt = 0; nt < 8; ++nt) {
                const int n0 = wn * 64 + nt * 8 + g;
                float y0, y1;
                if (TRANSB) {
                    y0 = Bc[n0 * ASTR + kk + t];
                    y1 = Bc[n0 * ASTR + kk + t + 4];
                } else {
                    const int nsw = n0 ^ (8 * t);
                    y0 = Bc[(kk + t) * 128 + nsw];
                    y1 = Bc[(kk + t + 4) * 128 + nsw];
                }
                unsigned b_h[2], b_l[2];
                splitP<PASSES>(y0, b_h[0], b_l[0]);
                splitP<PASSES>(y1, b_h[1], b_l[1]);
                #pragma unroll
                for (int mt = 0; mt < 4; ++mt) {
                    MMA_TF32(acc[mt][nt], a_h[mt], b_h);
                    if (PASSES >= 2) MMA_TF32(acc[mt][nt], a_h[mt], b_l);
                    if (PASSES >= 3) MMA_TF32(acc[mt][nt], a_l[mt], b_h);
                }
            }
        }
    }

    // epilogue
    #pragma unroll
    for (int mt = 0; mt < 4; ++mt) {
        #pragma unroll
        for (int nt = 0; nt < 8; ++nt) {
            const int row0 = blockIdx.y * 128 + wm * 64 + mt * 16 + g;
            const int col  = blockIdx.x * 128 + wn * 64 + nt * 8 + t * 2;
            float bv0 = 0.f, bv1 = 0.f;
            if (bias) { bv0 = bias[col]; bv1 = bias[col + 1]; }
            float2 v0 = make_float2(acc[mt][nt][0] * alpha + bv0,
                                    acc[mt][nt][1] * alpha + bv1);
            *(float2*)(Cb + (size_t)row0 * ldc + col) = v0;
            float2 v1 = make_float2(acc[mt][nt][2] * alpha + bv0,
                                    acc[mt][nt][3] * alpha + bv1);
            *(float2*)(Cb + (size_t)(row0 + 8) * ldc + col) = v1;
        }
    }
}

// ---------------------------------------------------------------------------
// Fused softmax + threshold mask + renorm (in place) + sparse nnz extraction.
// __expf everywhere: exp noise ~1e-6 is dominated by the ~1e-5 logit noise
// from the truncated tf32 split, which empirically causes zero mask flips.
// ---------------------------------------------------------------------------
__global__ __launch_bounds__(256) void softmax_mask_kernel(
    float* __restrict__ P, int* __restrict__ scnt,
    int* __restrict__ sidx, float* __restrict__ sval)
{
    const int row = blockIdx.x;
    float* Pr = P + (size_t)row * Ss;
    const int tid = threadIdx.x;
    const int lane = tid & 31, wid = tid >> 5;

    __shared__ float sv[8];
    __shared__ int   si[8];
    __shared__ int   cnt;
    if (tid == 0) cnt = 0;

    float4 lv = ((const float4*)Pr)[tid];
    float l[4] = {lv.x, lv.y, lv.z, lv.w};

    float m = l[0]; int mi = 4 * tid;
    #pragma unroll
    for (int r = 1; r < 4; ++r)
        if (l[r] > m) { m = l[r]; mi = 4 * tid + r; }
    #pragma unroll
    for (int o = 16; o > 0; o >>= 1) {
        float ov = __shfl_down_sync(0xffffffffu, m, o);
        int   oi = __shfl_down_sync(0xffffffffu, mi, o);
        if (ov > m || (ov == m && oi < mi)) { m = ov; mi = oi; }
    }
    if (lane == 0) { sv[wid] = m; si[wid] = mi; }
    __syncthreads();
    if (wid == 0) {
        float v = (lane < 8) ? sv[lane] : -3.4e38f;
        int vi  = (lane < 8) ? si[lane] : 0x7fffffff;
        #pragma unroll
        for (int o = 4; o > 0; o >>= 1) {
            float ov = __shfl_down_sync(0xffffffffu, v, o);
            int   oi = __shfl_down_sync(0xffffffffu, vi, o);
            if (ov > v || (ov == v && oi < vi)) { v = ov; vi = oi; }
        }
        if (lane == 0) { sv[0] = v; si[0] = vi; }
    }
    __syncthreads();
    const float rowmax = sv[0];
    const int argmax = si[0];
    __syncthreads();

    float e[4]; float zsum = 0.f;
    #pragma unroll
    for (int r = 0; r < 4; ++r) { e[r] = __expf(l[r] - rowmax); zsum += e[r]; }
    #pragma unroll
    for (int o = 16; o > 0; o >>= 1) zsum += __shfl_xor_sync(0xffffffffu, zsum, o);
    if (lane == 0) sv[wid] = zsum;
    __syncthreads();
    float Z = 0.f;
    #pragma unroll
    for (int w = 0; w < 8; ++w) Z += sv[w];
    __syncthreads();

    const float invZ = 1.0f / Z;
    float p[4]; float msum = 0.f;
    #pragma unroll
    for (int r = 0; r < 4; ++r) {
        p[r] = e[r] * invZ;
        if (p[r] > 0.1f) msum += p[r];
    }
    #pragma unroll
    for (int o = 16; o > 0; o >>= 1) msum += __shfl_xor_sync(0xffffffffu, msum, o);
    if (lane == 0) sv[wid] = msum;
    __syncthreads();
    float sumMask = 0.f;
    #pragma unroll
    for (int w = 0; w < 8; ++w) sumMask += sv[w];

    float4 ov;
    if (sumMask > 0.f) {
        const float inv = 1.0f / sumMask;
        float q[4];
        #pragma unroll
        for (int r = 0; r < 4; ++r)
            q[r] = (p[r] > 0.1f) ? p[r] * inv : 0.f;
        ov.x = q[0]; ov.y = q[1]; ov.z = q[2]; ov.w = q[3];
        #pragma unroll
        for (int r = 0; r < 4; ++r) {
            if (p[r] > 0.1f) {
                int pos = atomicAdd(&cnt, 1);
                if (pos < NNZ_CAP) {
                    sidx[(size_t)row * NNZ_CAP + pos] = 4 * tid + r;
                    sval[(size_t)row * NNZ_CAP + pos] = q[r];
                }
            }
        }
    } else {
        ov.x = (4 * tid + 0 == argmax) ? 1.f : 0.f;
        ov.y = (4 * tid + 1 == argmax) ? 1.f : 0.f;
        ov.z = (4 * tid + 2 == argmax) ? 1.f : 0.f;
        ov.w = (4 * tid + 3 == argmax) ? 1.f : 0.f;
        if (argmax >= 4 * tid && argmax < 4 * tid + 4) {
            int pos = atomicAdd(&cnt, 1);
            if (pos < NNZ_CAP) {
                sidx[(size_t)row * NNZ_CAP + pos] = argmax;
                sval[(size_t)row * NNZ_CAP + pos] = 1.0f;
            }
        }
    }
    ((float4*)Pr)[tid] = ov;

    __syncthreads();
    if (tid == 0) scnt[row] = (cnt < NNZ_CAP) ? cnt : NNZ_CAP;
}

// ---------------------------------------------------------------------------
// Sparse AV: one warp per attention row. out[i,:] = sum_k val_k * V[idx_k,:]
// ---------------------------------------------------------------------------
__global__ __launch_bounds__(256) void av_sparse_kernel(
    const int* __restrict__ scnt, const int* __restrict__ sidx,
    const float* __restrict__ sval, const float* __restrict__ qkv,
    float* __restrict__ ao)
{
    const int r = blockIdx.x * 8 + (threadIdx.x >> 5);
    const int lane = threadIdx.x & 31;

    const int bh = r >> 10, i = r & 1023;
    const int b = bh >> 4, h = bh & 15;
    const float* Vb = qkv + (size_t)b * Ss * QKVN + 2 * Ee + h * DH;

    const int c = scnt[r];
    float a0 = 0.f, a1 = 0.f;
    for (int k = 0; k < c; ++k) {
        const int j = sidx[(size_t)r * NNZ_CAP + k];
        const float v = sval[(size_t)r * NNZ_CAP + k];
        const float* Vr = Vb + (size_t)j * QKVN;
        a0 += v * Vr[lane];
        a1 += v * Vr[lane + 32];
    }
    float* Or = ao + (size_t)(b * Ss + i) * Ee + h * DH;
    Or[lane] = a0;
    Or[lane + 32] = a1;
}

// ---------------------------------------------------------------------------
// Launch
// ---------------------------------------------------------------------------
static float* sym_addr(const void* sym)
{
    void* p = nullptr;
    cudaGetSymbolAddress(&p, sym);
    return (float*)p;
}

extern "C" void kernel_launch(void* const* d_in, const int* in_sizes, int n_in,
                              void* d_out, int out_size)
{
    const float* x      = (const float*)d_in[0];
    const float* w_qkv  = (const float*)d_in[1];
    const float* b_qkv  = (const float*)d_in[2];
    const float* w_proj = (const float*)d_in[3];
    const float* b_proj = (const float*)d_in[4];

    float* qkv = sym_addr(g_qkv);
    float* ao  = sym_addr(g_ao);
    int*   scnt = (int*)sym_addr(g_scnt);
    int*   sidx = (int*)sym_addr(g_sidx);
    float* sval = sym_addr(g_sval);

    const size_t OUT_N  = (size_t)Bb * Ss * Ee;
    const size_t ATTN_N = (size_t)Bb * Hh * Ss * Ss;

    float* out = (float*)d_out;
    float* P;
    float* mainOut;
    if ((size_t)out_size >= OUT_N + ATTN_N) {
        mainOut = out;
        P = out + OUT_N;
    } else if ((size_t)out_size == ATTN_N) {
        mainOut = sym_addr(g_spill);
        P = out;
    } else {
        mainOut = out;
        P = sym_addr(g_P);
    }

    const int smemN = G1_SMEM_N * sizeof(float);   // 104448
    const int smemT = G1_SMEM_T * sizeof(float);   // 110592
    cudaFuncSetAttribute(gemm_g1_kernel<0, 0, 3>,
                         cudaFuncAttributeMaxDynamicSharedMemorySize, smemN);
    cudaFuncSetAttribute(gemm_g1_kernel<0, 0, 1>,
                         cudaFuncAttributeMaxDynamicSharedMemorySize, smemN);
    cudaFuncSetAttribute(gemm_g1_kernel<1, 1, 3>,
                         cudaFuncAttributeMaxDynamicSharedMemorySize, smemT);

    // 1a. Q,K projection: [4096,1024] @ [1024,2048] + bias  (tf32x3 — feeds mask)
    {
        dim3 grid(2048 / 128, MROWS / 128, 1);
        gemm_g1_kernel<0, 0, 3><<<grid, 128, smemN>>>(
            x, w_qkv, b_qkv, qkv, Ee, Ee, QKVN, QKVN, 1.0f);
    }
    // 1b. V projection: [4096,1024] @ [1024,1024] + bias  (tf32x1 — output only)
    {
        dim3 grid(1024 / 128, MROWS / 128, 1);
        gemm_g1_kernel<0, 0, 1><<<grid, 128, smemN>>>(
            x, w_qkv + 2048, b_qkv + 2048, qkv + 2048, Ee, Ee, QKVN, QKVN, 1.0f);
    }
    // 2. QK^T logits per (b,h), alpha = Dh^-0.5  (tf32x3)
    {
        dim3 grid(Ss / 128, Ss / 128, Bb * Hh);
        gemm_g1_kernel<1, 1, 3><<<grid, 128, smemT>>>(
            qkv, qkv, nullptr, P, DH, QKVN, QKVN, Ss, 0.125f);
    }
    // 3. fused softmax + threshold mask + renorm + sparse extraction (__expf)
    softmax_mask_kernel<<<NROWS, 256>>>(P, scnt, sidx, sval);
    // 4. sparse AV (<= 9 nnz per row guaranteed)
    av_sparse_kernel<<<NROWS / 8, 256>>>(scnt, sidx, sval, qkv, ao);
    // 5. output projection: [4096,1024] @ [1024,1024] + bias  (tf32x1 — out only)
    {
        dim3 grid(Ee / 128, MROWS / 128, 1);
        gemm_g1_kernel<0, 0, 1><<<grid, 128, smemN>>>(
            ao, w_proj, b_proj, mainOut, Ee, Ee, Ee, Ee, 1.0f);
    }
}

// round 11
// speedup vs baseline: 1.1978x; 1.0769x over previous
#include <cuda_runtime.h>
#include <math.h>

// Problem constants
#define Bb 4
#define Ss 1024
#define Ee 1024
#define Hh 16
#define DH 64
#define MROWS (Bb * Ss)      // 4096
#define QKVN (3 * Ee)        // 3072
#define NROWS (Bb * Hh * Ss) // 65536 attention rows
#define NNZ_CAP 16

// Scratch
__device__ float g_qkv[(size_t)MROWS * QKVN];
__device__ float g_P[(size_t)Bb * Hh * Ss * Ss];
__device__ float g_ao[(size_t)MROWS * Ee];
__device__ float g_spill[(size_t)MROWS * Ee];
__device__ int   g_scnt[NROWS];
__device__ int   g_sidx[(size_t)NROWS * NNZ_CAP];
__device__ float g_sval[(size_t)NROWS * NNZ_CAP];

// ---------------------------------------------------------------------------
// Common helpers
// ---------------------------------------------------------------------------
__device__ __forceinline__ unsigned f2tf32_rna(float x) {
    unsigned u;
    asm("cvt.rna.tf32.f32 %0, %1;" : "=r"(u) : "f"(x));
    return u;
}

template <int PASSES>
__device__ __forceinline__ void splitP(float x, unsigned& h, unsigned& l) {
    if (PASSES == 1) {
        h = f2tf32_rna(x);            // single pass: round-to-nearest tf32
        l = 0u;
    } else {
        unsigned hu = __float_as_uint(x) & 0xffffe000u;  // truncate
        h = hu;
        l = __float_as_uint(x - __uint_as_float(hu));    // residual
    }
}

#define MMA_TF32(cc, aa, bb)                                              \
    asm volatile(                                                          \
        "mma.sync.aligned.m16n8k8.row.col.f32.tf32.tf32.f32 "             \
        "{%0,%1,%2,%3}, {%4,%5,%6,%7}, {%8,%9}, {%0,%1,%2,%3};"           \
        : "+f"(cc[0]), "+f"(cc[1]), "+f"(cc[2]), "+f"(cc[3])              \
        : "r"(aa[0]), "r"(aa[1]), "r"(aa[2]), "r"(aa[3]),                 \
          "r"(bb[0]), "r"(bb[1]))

#define CP_ASYNC16(dst, src)                                              \
    asm volatile("cp.async.cg.shared.global [%0], [%1], 16;"              \
                 :: "r"(dst), "l"(src))
#define CP_COMMIT() asm volatile("cp.async.commit_group;")
#define CP_WAIT_ALL() asm volatile("cp.async.wait_group 0;")
#define CP_WAIT1() asm volatile("cp.async.wait_group 1;")

// ===========================================================================
// G1: 128x128 CTA tile, BK=32, 128 threads (4 warps as 2x2, warp tile 64x64).
//   3-stage cp.async pipeline, single __syncthreads per K-iter.
//   PASSES: 3 = full tf32x3 (fp32-accurate), 1 = plain tf32 (rna).
// MODE: 0 = plain (C=alpha*A@B(+bias)),  1 = QK^T per (b,h)
// ===========================================================================
#define ASTR 36
#define G1_A_TILE (128 * ASTR)        // 4608 floats
#define G1_BT_TILE (128 * ASTR)       // 4608
#define G1_BN_TILE (32 * 128)         // 4096
#define G1_SMEM_T (3 * (G1_A_TILE + G1_BT_TILE))   // 110592 B
#define G1_SMEM_N (3 * (G1_A_TILE + G1_BN_TILE))   // 104448 B

template <int TRANSB>
__device__ __forceinline__ void g1_load(
    const float* __restrict__ Abase, const float* __restrict__ Bbase,
    int lda, int ldb, int k0, float* As, float* Bs, int tid)
{
    // A: 128 x 32  (128 threads -> 8 x float4 each)
    {
        const int row = tid >> 3;               // 0..15
        const int col = (tid & 7) * 4;
        const float* src = Abase + (size_t)row * lda + k0 + col;
        unsigned dst = (unsigned)__cvta_generic_to_shared(As + row * ASTR + col);
        #pragma unroll
        for (int r = 0; r < 8; ++r)
            CP_ASYNC16(dst + r * 16 * ASTR * 4, src + (size_t)r * 16 * lda);
    }
    if (TRANSB) {
        const int row = tid >> 3;
        const int col = (tid & 7) * 4;
        const float* src = Bbase + (size_t)row * ldb + k0 + col;
        unsigned dst = (unsigned)__cvta_generic_to_shared(Bs + row * ASTR + col);
        #pragma unroll
        for (int r = 0; r < 8; ++r)
            CP_ASYNC16(dst + r * 16 * ASTR * 4, src + (size_t)r * 16 * ldb);
    } else {
        #pragma unroll
        for (int r = 0; r < 8; ++r) {
            const int elem = r * 128 + tid;
            const int kr = elem >> 5;
            const int c4 = (elem & 31) * 4;
            const float* src = Bbase + (size_t)(k0 + kr) * ldb + c4;
            unsigned dst = (unsigned)__cvta_generic_to_shared(
                Bs + kr * 128 + (c4 ^ (8 * (kr & 3))));
            CP_ASYNC16(dst, src);
        }
    }
}

template <int MODE, int TRANSB, int PASSES>
__global__ __launch_bounds__(128) void gemm_g1_kernel(
    const float* __restrict__ A, const float* __restrict__ B,
    const float* __restrict__ bias, float* __restrict__ C,
    int K, int lda, int ldb, int ldc, float alpha)
{
    extern __shared__ float sm[];
    const int B_TILE = TRANSB ? G1_BT_TILE : G1_BN_TILE;
    float* As = sm;                         // 3 stages
    float* Bs = sm + 3 * G1_A_TILE;         // 3 stages

    const int tid = threadIdx.x;
    const int z = blockIdx.z;

    const float* Ab;
    const float* Bbp;
    float* Cb;
    if (MODE == 0) {
        Ab = A; Bbp = B; Cb = C;
    } else {                              // QK^T per (b,h)
        const int b = z >> 4, h = z & 15;
        Ab  = A + (size_t)b * Ss * QKVN + h * DH;
        Bbp = B + (size_t)b * Ss * QKVN + Ee + h * DH;
        Cb  = C + (size_t)z * Ss * Ss;
    }

    const float* Abase = Ab + (size_t)blockIdx.y * 128 * lda;
    const float* Bbase = TRANSB ? (Bbp + (size_t)blockIdx.x * 128 * ldb)
                                : (Bbp + blockIdx.x * 128);

    const int warp = tid >> 5, lane = tid & 31;
    const int wm = warp >> 1, wn = warp & 1;      // 2x2 warps, warp tile 64x64
    const int g = lane >> 2, t = lane & 3;

    float acc[4][8][4];
    #pragma unroll
    for (int mt = 0; mt < 4; ++mt)
        #pragma unroll
        for (int nt = 0; nt < 8; ++nt)
            #pragma unroll
            for (int r = 0; r < 4; ++r) acc[mt][nt][r] = 0.f;

    const int KT = K >> 5;

    g1_load<TRANSB>(Abase, Bbase, lda, ldb, 0, As, Bs, tid);
    CP_COMMIT();
    if (KT > 1) {
        g1_load<TRANSB>(Abase, Bbase, lda, ldb, 32,
                        As + G1_A_TILE, Bs + B_TILE, tid);
        CP_COMMIT();
    }

    for (int kt = 0; kt < KT; ++kt) {
        if (kt < KT - 1) CP_WAIT1(); else CP_WAIT_ALL();
        __syncthreads();

        if (kt + 2 < KT) {
            const int buf = (kt + 2) % 3;
            g1_load<TRANSB>(Abase, Bbase, lda, ldb, (kt + 2) * 32,
                            As + buf * G1_A_TILE, Bs + buf * B_TILE, tid);
            CP_COMMIT();
        }

        const float* Ac = As + (kt % 3) * G1_A_TILE;
        const float* Bc = Bs + (kt % 3) * B_TILE;

        #pragma unroll
        for (int kk = 0; kk < 32; kk += 8) {
            unsigned a_h[4][4], a_l[4][4];
            const int kcol = kk + t;
            #pragma unroll
            for (int mt = 0; mt < 4; ++mt) {
                const int m0 = wm * 64 + mt * 16 + g;
                splitP<PASSES>(Ac[m0 * ASTR + kcol],           a_h[mt][0], a_l[mt][0]);
                splitP<PASSES>(Ac[(m0 + 8) * ASTR + kcol],     a_h[mt][1], a_l[mt][1]);
                splitP<PASSES>(Ac[m0 * ASTR + kcol + 4],       a_h[mt][2], a_l[mt][2]);
                splitP<PASSES>(Ac[(m0 + 8) * ASTR + kcol + 4], a_h[mt][3], a_l[mt][3]);
            }
            #pragma unroll
            for (int nt = 0; nt < 8; ++nt) {
                const int n0 = wn * 64 + nt * 8 + g;
                float y0, y1;
                if (TRANSB) {
                    y0 = Bc[n0 * ASTR + kk + t];
                    y1 = Bc[n0 * ASTR + kk + t + 4];
                } else {
                    const int nsw = n0 ^ (8 * t);
                    y0 = Bc[(kk + t) * 128 + nsw];
                    y1 = Bc[(kk + t + 4) * 128 + nsw];
                }
                unsigned b_h[2], b_l[2];
                splitP<PASSES>(y0, b_h[0], b_l[0]);
                splitP<PASSES>(y1, b_h[1], b_l[1]);
                #pragma unroll
                for (int mt = 0; mt < 4; ++mt) {
                    MMA_TF32(acc[mt][nt], a_h[mt], b_h);
                    if (PASSES >= 2) MMA_TF32(acc[mt][nt], a_h[mt], b_l);
                    if (PASSES >= 3) MMA_TF32(acc[mt][nt], a_l[mt], b_h);
                }
            }
        }
    }

    // epilogue
    #pragma unroll
    for (int mt = 0; mt < 4; ++mt) {
        #pragma unroll
        for (int nt = 0; nt < 8; ++nt) {
            const int row0 = blockIdx.y * 128 + wm * 64 + mt * 16 + g;
            const int col  = blockIdx.x * 128 + wn * 64 + nt * 8 + t * 2;
            float bv0 = 0.f, bv1 = 0.f;
            if (bias) { bv0 = bias[col]; bv1 = bias[col + 1]; }
            float2 v0 = make_float2(acc[mt][nt][0] * alpha + bv0,
                                    acc[mt][nt][1] * alpha + bv1);
            *(float2*)(Cb + (size_t)row0 * ldc + col) = v0;
            float2 v1 = make_float2(acc[mt][nt][2] * alpha + bv0,
                                    acc[mt][nt][3] * alpha + bv1);
            *(float2*)(Cb + (size_t)(row0 + 8) * ldc + col) = v1;
        }
    }
}

// ---------------------------------------------------------------------------
// Warp-per-row softmax + threshold mask + renorm (in place) + sparse extract.
// One warp owns a 1024-col row: 32 register-resident values per thread,
// shuffle-only reductions, prefix-scan extraction, no smem, no block syncs.
// ---------------------------------------------------------------------------
__global__ __launch_bounds__(256) void softmax_mask_kernel(
    float* __restrict__ P, int* __restrict__ scnt,
    int* __restrict__ sidx, float* __restrict__ sval)
{
    const int r = blockIdx.x * 8 + (threadIdx.x >> 5);
    const int lane = threadIdx.x & 31;
    float* Pr = P + (size_t)r * Ss;

    // load 32 values: cols it*128 + lane*4 + j
    float l[32];
    #pragma unroll
    for (int it = 0; it < 8; ++it) {
        float4 v = __ldcs((const float4*)(Pr + it * 128 + lane * 4));
        l[it * 4 + 0] = v.x; l[it * 4 + 1] = v.y;
        l[it * 4 + 2] = v.z; l[it * 4 + 3] = v.w;
    }

    // ---- max + argmax (first occurrence) ----
    float m = l[0]; int mi = lane * 4;
    #pragma unroll
    for (int it = 0; it < 8; ++it)
        #pragma unroll
        for (int j = 0; j < 4; ++j) {
            const int col = it * 128 + lane * 4 + j;
            if (l[it * 4 + j] > m || (l[it * 4 + j] == m && col < mi)) {
                m = l[it * 4 + j]; mi = col;
            }
        }
    #pragma unroll
    for (int o = 16; o > 0; o >>= 1) {
        float ov = __shfl_xor_sync(0xffffffffu, m, o);
        int   oi = __shfl_xor_sync(0xffffffffu, mi, o);
        if (ov > m || (ov == m && oi < mi)) { m = ov; mi = oi; }
    }

    // ---- exp + Z ----
    float zs = 0.f;
    #pragma unroll
    for (int i = 0; i < 32; ++i) { l[i] = __expf(l[i] - m); zs += l[i]; }
    #pragma unroll
    for (int o = 16; o > 0; o >>= 1) zs += __shfl_xor_sync(0xffffffffu, zs, o);
    const float invZ = 1.0f / zs;

    // ---- p, masked sum, local count ----
    float ms = 0.f; int cl = 0;
    #pragma unroll
    for (int i = 0; i < 32; ++i) {
        l[i] *= invZ;                       // l[] now holds p
        if (l[i] > 0.1f) { ms += l[i]; ++cl; }
    }
    #pragma unroll
    for (int o = 16; o > 0; o >>= 1) ms += __shfl_xor_sync(0xffffffffu, ms, o);

    // ---- warp exclusive prefix scan of counts ----
    int inc = cl;
    #pragma unroll
    for (int o = 1; o < 32; o <<= 1) {
        int n = __shfl_up_sync(0xffffffffu, inc, o);
        if (lane >= o) inc += n;
    }
    const int excl = inc - cl;
    const int total = __shfl_sync(0xffffffffu, inc, 31);

    if (total > 0) {
        const float inv = 1.0f / ms;
        int pos = excl;
        #pragma unroll
        for (int it = 0; it < 8; ++it) {
            float4 o4;
            float q[4];
            #pragma unroll
            for (int j = 0; j < 4; ++j) {
                const float p = l[it * 4 + j];
                const bool sel = p > 0.1f;
                q[j] = sel ? p * inv : 0.f;
                if (sel) {
                    if (pos < NNZ_CAP) {
                        const int col = it * 128 + lane * 4 + j;
                        sidx[(size_t)r * NNZ_CAP + pos] = col;
                        sval[(size_t)r * NNZ_CAP + pos] = q[j];
                    }
                    ++pos;
                }
            }
            o4.x = q[0]; o4.y = q[1]; o4.z = q[2]; o4.w = q[3];
            __stcs((float4*)(Pr + it * 128 + lane * 4), o4);
        }
    } else {
        #pragma unroll
        for (int it = 0; it < 8; ++it) {
            float4 o4;
            #pragma unroll
            for (int j = 0; j < 4; ++j) {
                const int col = it * 128 + lane * 4 + j;
                ((float*)&o4)[j] = (col == mi) ? 1.f : 0.f;
            }
            __stcs((float4*)(Pr + it * 128 + lane * 4), o4);
        }
        if (lane == 0) {
            sidx[(size_t)r * NNZ_CAP] = mi;
            sval[(size_t)r * NNZ_CAP] = 1.0f;
        }
    }
    if (lane == 0) {
        int c = (total > 0) ? total : 1;
        scnt[r] = (c < NNZ_CAP) ? c : NNZ_CAP;
    }
}

// ---------------------------------------------------------------------------
// Sparse AV: one warp per attention row. out[i,:] = sum_k val_k * V[idx_k,:]
// ---------------------------------------------------------------------------
__global__ __launch_bounds__(256) void av_sparse_kernel(
    const int* __restrict__ scnt, const int* __restrict__ sidx,
    const float* __restrict__ sval, const float* __restrict__ qkv,
    float* __restrict__ ao)
{
    const int r = blockIdx.x * 8 + (threadIdx.x >> 5);
    const int lane = threadIdx.x & 31;

    const int bh = r >> 10, i = r & 1023;
    const int b = bh >> 4, h = bh & 15;
    const float* Vb = qkv + (size_t)b * Ss * QKVN + 2 * Ee + h * DH;

    const int c = scnt[r];
    float a0 = 0.f, a1 = 0.f;
    for (int k = 0; k < c; ++k) {
        const int j = sidx[(size_t)r * NNZ_CAP + k];
        const float v = sval[(size_t)r * NNZ_CAP + k];
        const float* Vr = Vb + (size_t)j * QKVN;
        a0 += v * Vr[lane];
        a1 += v * Vr[lane + 32];
    }
    float* Or = ao + (size_t)(b * Ss + i) * Ee + h * DH;
    Or[lane] = a0;
    Or[lane + 32] = a1;
}

// ---------------------------------------------------------------------------
// Launch
// ---------------------------------------------------------------------------
static float* sym_addr(const void* sym)
{
    void* p = nullptr;
    cudaGetSymbolAddress(&p, sym);
    return (float*)p;
}

extern "C" void kernel_launch(void* const* d_in, const int* in_sizes, int n_in,
                              void* d_out, int out_size)
{
    const float* x      = (const float*)d_in[0];
    const float* w_qkv  = (const float*)d_in[1];
    const float* b_qkv  = (const float*)d_in[2];
    const float* w_proj = (const float*)d_in[3];
    const float* b_proj = (const float*)d_in[4];

    float* qkv = sym_addr(g_qkv);
    float* ao  = sym_addr(g_ao);
    int*   scnt = (int*)sym_addr(g_scnt);
    int*   sidx = (int*)sym_addr(g_sidx);
    float* sval = sym_addr(g_sval);

    const size_t OUT_N  = (size_t)Bb * Ss * Ee;
    const size_t ATTN_N = (size_t)Bb * Hh * Ss * Ss;

    float* out = (float*)d_out;
    float* P;
    float* mainOut;
    if ((size_t)out_size >= OUT_N + ATTN_N) {
        mainOut = out;
        P = out + OUT_N;
    } else if ((size_t)out_size == ATTN_N) {
        mainOut = sym_addr(g_spill);
        P = out;
    } else {
        mainOut = out;
        P = sym_addr(g_P);
    }

    const int smemN = G1_SMEM_N * sizeof(float);   // 104448
    const int smemT = G1_SMEM_T * sizeof(float);   // 110592
    cudaFuncSetAttribute(gemm_g1_kernel<0, 0, 3>,
                         cudaFuncAttributeMaxDynamicSharedMemorySize, smemN);
    cudaFuncSetAttribute(gemm_g1_kernel<0, 0, 1>,
                         cudaFuncAttributeMaxDynamicSharedMemorySize, smemN);
    cudaFuncSetAttribute(gemm_g1_kernel<1, 1, 3>,
                         cudaFuncAttributeMaxDynamicSharedMemorySize, smemT);

    // 1a. Q,K projection: [4096,1024] @ [1024,2048] + bias  (tf32x3 — feeds mask)
    {
        dim3 grid(2048 / 128, MROWS / 128, 1);
        gemm_g1_kernel<0, 0, 3><<<grid, 128, smemN>>>(
            x, w_qkv, b_qkv, qkv, Ee, Ee, QKVN, QKVN, 1.0f);
    }
    // 1b. V projection: [4096,1024] @ [1024,1024] + bias  (tf32x1 — output only)
    {
        dim3 grid(1024 / 128, MROWS / 128, 1);
        gemm_g1_kernel<0, 0, 1><<<grid, 128, smemN>>>(
            x, w_qkv + 2048, b_qkv + 2048, qkv + 2048, Ee, Ee, QKVN, QKVN, 1.0f);
    }
    // 2. QK^T logits per (b,h), alpha = Dh^-0.5  (tf32x3)
    {
        dim3 grid(Ss / 128, Ss / 128, Bb * Hh);
        gemm_g1_kernel<1, 1, 3><<<grid, 128, smemT>>>(
            qkv, qkv, nullptr, P, DH, QKVN, QKVN, Ss, 0.125f);
    }
    // 3. warp-per-row softmax + threshold mask + renorm + sparse extraction
    softmax_mask_kernel<<<NROWS / 8, 256>>>(P, scnt, sidx, sval);
    // 4. sparse AV (<= 9 nnz per row guaranteed)
    av_sparse_kernel<<<NROWS / 8, 256>>>(scnt, sidx, sval, qkv, ao);
    // 5. output projection: [4096,1024] @ [1024,1024] + bias  (tf32x1 — out only)
    {
        dim3 grid(Ee / 128, MROWS / 128, 1);
        gemm_g1_kernel<0, 0, 1><<<grid, 128, smemN>>>(
            ao, w_proj, b_proj, mainOut, Ee, Ee, Ee, Ee, 1.0f);
    }
}

// round 13
// speedup vs baseline: 1.2021x; 1.0036x over previous
#include <cuda_runtime.h>
#include <math.h>
#include <stdint.h>

// Problem constants
#define Bb 4
#define Ss 1024
#define Ee 1024
#define Hh 16
#define DH 64
#define MROWS (Bb * Ss)      // 4096
#define QKVN (3 * Ee)        // 3072
#define NROWS (Bb * Hh * Ss) // 65536 attention rows
#define NNZ_CAP 16

// Scratch
__device__ float g_qkv[(size_t)MROWS * QKVN];
__device__ float g_P[(size_t)Bb * Hh * Ss * Ss];
__device__ float g_ao[(size_t)MROWS * Ee];
__device__ float g_spill[(size_t)MROWS * Ee];
__device__ int   g_scnt[NROWS];
__device__ int   g_sidx[(size_t)NROWS * NNZ_CAP];
__device__ float g_sval[(size_t)NROWS * NNZ_CAP];

// ---------------------------------------------------------------------------
// Common helpers
// ---------------------------------------------------------------------------
__device__ __forceinline__ unsigned f2tf32_rna(float x) {
    unsigned u;
    asm("cvt.rna.tf32.f32 %0, %1;" : "=r"(u) : "f"(x));
    return u;
}

template <int PASSES>
__device__ __forceinline__ void splitP(float x, unsigned& h, unsigned& l) {
    if (PASSES == 1) {
        h = f2tf32_rna(x);            // single pass: round-to-nearest tf32
        l = 0u;
    } else {
        unsigned hu = __float_as_uint(x) & 0xffffe000u;  // truncate
        h = hu;
        l = __float_as_uint(x - __uint_as_float(hu));    // residual
    }
}

#define MMA_TF32(cc, aa, bb)                                              \
    asm volatile(                                                          \
        "mma.sync.aligned.m16n8k8.row.col.f32.tf32.tf32.f32 "             \
        "{%0,%1,%2,%3}, {%4,%5,%6,%7}, {%8,%9}, {%0,%1,%2,%3};"           \
        : "+f"(cc[0]), "+f"(cc[1]), "+f"(cc[2]), "+f"(cc[3])              \
        : "r"(aa[0]), "r"(aa[1]), "r"(aa[2]), "r"(aa[3]),                 \
          "r"(bb[0]), "r"(bb[1]))

#define CP_ASYNC16(dst, src)                                              \
    asm volatile("cp.async.cg.shared.global [%0], [%1], 16;"              \
                 :: "r"(dst), "l"(src))
#define CP_COMMIT() asm volatile("cp.async.commit_group;")
#define CP_WAIT_ALL() asm volatile("cp.async.wait_group 0;")
#define CP_WAIT1() asm volatile("cp.async.wait_group 1;")

// ===========================================================================
// G1 mainloop as a device function: 128x128 CTA tile, BK=32, 128 threads
// (4 warps 2x2, warp tile 64x64), 3-stage cp.async pipeline.
//   PASSES: 3 = tf32x3 (fp32-accurate), 1 = plain tf32 (rna).
// ===========================================================================
#define ASTR 36
#define G1_A_TILE (128 * ASTR)        // 4608 floats
#define G1_BT_TILE (128 * ASTR)       // 4608
#define G1_BN_TILE (32 * 128)         // 4096
#define G1_SMEM_T (3 * (G1_A_TILE + G1_BT_TILE))   // 110592 B
#define G1_SMEM_N (3 * (G1_A_TILE + G1_BN_TILE))   // 104448 B

template <int TRANSB>
__device__ __forceinline__ void g1_load(
    const float* __restrict__ Abase, const float* __restrict__ Bbase,
    int lda, int ldb, int k0, float* As, float* Bs, int tid)
{
    // A: 128 x 32  (128 threads -> 8 x float4 each)
    {
        const int row = tid >> 3;               // 0..15
        const int col = (tid & 7) * 4;
        const float* src = Abase + (size_t)row * lda + k0 + col;
        unsigned dst = (unsigned)__cvta_generic_to_shared(As + row * ASTR + col);
        #pragma unroll
        for (int r = 0; r < 8; ++r)
            CP_ASYNC16(dst + r * 16 * ASTR * 4, src + (size_t)r * 16 * lda);
    }
    if (TRANSB) {
        const int row = tid >> 3;
        const int col = (tid & 7) * 4;
        const float* src = Bbase + (size_t)row * ldb + k0 + col;
        unsigned dst = (unsigned)__cvta_generic_to_shared(Bs + row * ASTR + col);
        #pragma unroll
        for (int r = 0; r < 8; ++r)
            CP_ASYNC16(dst + r * 16 * ASTR * 4, src + (size_t)r * 16 * ldb);
    } else {
        #pragma unroll
        for (int r = 0; r < 8; ++r) {
            const int elem = r * 128 + tid;
            const int kr = elem >> 5;
            const int c4 = (elem & 31) * 4;
            const float* src = Bbase + (size_t)(k0 + kr) * ldb + c4;
            unsigned dst = (unsigned)__cvta_generic_to_shared(
                Bs + kr * 128 + (c4 ^ (8 * (kr & 3))));
            CP_ASYNC16(dst, src);
        }
    }
}

template <int TRANSB, int PASSES>
__device__ __forceinline__ void g1_run(
    const float* __restrict__ Abase, const float* __restrict__ Bbase,
    const float* __restrict__ bias, float* __restrict__ Cb,
    int K, int lda, int ldb, int ldc, float alpha,
    float* As, float* Bs, int colBase)
{
    const int B_TILE = TRANSB ? G1_BT_TILE : G1_BN_TILE;
    const int tid = threadIdx.x;
    const int warp = tid >> 5, lane = tid & 31;
    const int wm = warp >> 1, wn = warp & 1;      // 2x2 warps, warp tile 64x64
    const int g = lane >> 2, t = lane & 3;

    float acc[4][8][4];
    #pragma unroll
    for (int mt = 0; mt < 4; ++mt)
        #pragma unroll
        for (int nt = 0; nt < 8; ++nt)
            #pragma unroll
            for (int r = 0; r < 4; ++r) acc[mt][nt][r] = 0.f;

    const int KT = K >> 5;

    g1_load<TRANSB>(Abase, Bbase, lda, ldb, 0, As, Bs, tid);
    CP_COMMIT();
    if (KT > 1) {
        g1_load<TRANSB>(Abase, Bbase, lda, ldb, 32,
                        As + G1_A_TILE, Bs + B_TILE, tid);
        CP_COMMIT();
    }

    for (int kt = 0; kt < KT; ++kt) {
        if (kt < KT - 1) CP_WAIT1(); else CP_WAIT_ALL();
        __syncthreads();

        if (kt + 2 < KT) {
            const int buf = (kt + 2) % 3;
            g1_load<TRANSB>(Abase, Bbase, lda, ldb, (kt + 2) * 32,
                            As + buf * G1_A_TILE, Bs + buf * B_TILE, tid);
            CP_COMMIT();
        }

        const float* Ac = As + (kt % 3) * G1_A_TILE;
        const float* Bc = Bs + (kt % 3) * B_TILE;

        #pragma unroll
        for (int kk = 0; kk < 32; kk += 8) {
            unsigned a_h[4][4], a_l[4][4];
            const int kcol = kk + t;
            #pragma unroll
            for (int mt = 0; mt < 4; ++mt) {
                const int m0 = wm * 64 + mt * 16 + g;
                splitP<PASSES>(Ac[m0 * ASTR + kcol],           a_h[mt][0], a_l[mt][0]);
                splitP<PASSES>(Ac[(m0 + 8) * ASTR + kcol],     a_h[mt][1], a_l[mt][1]);
                splitP<PASSES>(Ac[m0 * ASTR + kcol + 4],       a_h[mt][2], a_l[mt][2]);
                splitP<PASSES>(Ac[(m0 + 8) * ASTR + kcol + 4], a_h[mt][3], a_l[mt][3]);
            }
            #pragma unroll
            for (int nt = 0; nt < 8; ++nt) {
                const int n0 = wn * 64 + nt * 8 + g;
                float y0, y1;
                if (TRANSB) {
                    y0 = Bc[n0 * ASTR + kk + t];
                    y1 = Bc[n0 * ASTR + kk + t + 4];
                } else {
                    const int nsw = n0 ^ (8 * t);
                    y0 = Bc[(kk + t) * 128 + nsw];
                    y1 = Bc[(kk + t + 4) * 128 + nsw];
                }
                unsigned b_h[2], b_l[2];
                splitP<PASSES>(y0, b_h[0], b_l[0]);
                splitP<PASSES>(y1, b_h[1], b_l[1]);
                #pragma unroll
                for (int mt = 0; mt < 4; ++mt) {
                    MMA_TF32(acc[mt][nt], a_h[mt], b_h);
                    if (PASSES >= 2) MMA_TF32(acc[mt][nt], a_h[mt], b_l);
                    if (PASSES >= 3) MMA_TF32(acc[mt][nt], a_l[mt], b_h);
                }
            }
        }
    }

    // epilogue
    #pragma unroll
    for (int mt = 0; mt < 4; ++mt) {
        #pragma unroll
        for (int nt = 0; nt < 8; ++nt) {
            const int row0 = blockIdx.y * 128 + wm * 64 + mt * 16 + g;
            const int col  = colBase + wn * 64 + nt * 8 + t * 2;
            float bv0 = 0.f, bv1 = 0.f;
            if (bias) { bv0 = bias[col]; bv1 = bias[col + 1]; }
            float2 v0 = make_float2(acc[mt][nt][0] * alpha + bv0,
                                    acc[mt][nt][1] * alpha + bv1);
            *(float2*)(Cb + (size_t)row0 * ldc + col) = v0;
            float2 v1 = make_float2(acc[mt][nt][2] * alpha + bv0,
                                    acc[mt][nt][3] * alpha + bv1);
            *(float2*)(Cb + (size_t)(row0 + 8) * ldc + col) = v1;
        }
    }
}

// ---------------------------------------------------------------------------
// Merged QKV projection: blockIdx.x < xsplit -> tf32x3 (Q,K cols, feed mask),
// else -> tf32x1 (V cols, output-only). One launch, better wave packing.
// ---------------------------------------------------------------------------
__global__ __launch_bounds__(128) void gemm_qkv_kernel(
    const float* __restrict__ A, const float* __restrict__ B,
    const float* __restrict__ bias, float* __restrict__ C,
    int K, int lda, int ldb, int ldc, int xsplit)
{
    extern __shared__ float sm[];
    float* As = sm;
    float* Bs = sm + 3 * G1_A_TILE;

    const float* Abase = A + (size_t)blockIdx.y * 128 * lda;
    const float* Bbase = B + blockIdx.x * 128;

    if ((int)blockIdx.x < xsplit)
        g1_run<0, 3>(Abase, Bbase, bias, C, K, lda, ldb, ldc, 1.0f,
                     As, Bs, blockIdx.x * 128);
    else
        g1_run<0, 1>(Abase, Bbase, bias, C, K, lda, ldb, ldc, 1.0f,
                     As, Bs, blockIdx.x * 128);
}

// ---------------------------------------------------------------------------
// Plain GEMM kernel (proj): tf32x1
// ---------------------------------------------------------------------------
__global__ __launch_bounds__(128) void gemm_x1_kernel(
    const float* __restrict__ A, const float* __restrict__ B,
    const float* __restrict__ bias, float* __restrict__ C,
    int K, int lda, int ldb, int ldc)
{
    extern __shared__ float sm[];
    float* As = sm;
    float* Bs = sm + 3 * G1_A_TILE;

    const float* Abase = A + (size_t)blockIdx.y * 128 * lda;
    const float* Bbase = B + blockIdx.x * 128;
    g1_run<0, 1>(Abase, Bbase, bias, C, K, lda, ldb, ldc, 1.0f,
                 As, Bs, blockIdx.x * 128);
}

// ---------------------------------------------------------------------------
// QK^T kernel: per (b,h), A = Q slice, B = K slice (transB), tf32x3
// ---------------------------------------------------------------------------
__global__ __launch_bounds__(128) void gemm_qkt_kernel(
    const float* __restrict__ qkv, float* __restrict__ P)
{
    extern __shared__ float sm[];
    float* As = sm;
    float* Bs = sm + 3 * G1_A_TILE;

    const int z = blockIdx.z;
    const int b = z >> 4, h = z & 15;
    const float* Ab  = qkv + (size_t)b * Ss * QKVN + h * DH;
    const float* Bbp = qkv + (size_t)b * Ss * QKVN + Ee + h * DH;
    float* Cb = P + (size_t)z * Ss * Ss;

    const float* Abase = Ab + (size_t)blockIdx.y * 128 * QKVN;
    const float* Bbase = Bbp + (size_t)blockIdx.x * 128 * QKVN;

    g1_run<1, 3>(Abase, Bbase, nullptr, Cb, DH, QKVN, QKVN, Ss, 0.125f,
                 As, Bs, blockIdx.x * 128);
}

// ---------------------------------------------------------------------------
// Warp-per-row softmax + threshold mask + renorm + sparse extract (proven).
// ---------------------------------------------------------------------------
__global__ __launch_bounds__(256) void softmax_mask_kernel(
    float* __restrict__ P, int* __restrict__ scnt,
    int* __restrict__ sidx, float* __restrict__ sval)
{
    const int r = blockIdx.x * 8 + (threadIdx.x >> 5);
    const int lane = threadIdx.x & 31;
    float* Pr = P + (size_t)r * Ss;

    float l[32];
    #pragma unroll
    for (int it = 0; it < 8; ++it) {
        float4 v = __ldcs((const float4*)(Pr + it * 128 + lane * 4));
        l[it * 4 + 0] = v.x; l[it * 4 + 1] = v.y;
        l[it * 4 + 2] = v.z; l[it * 4 + 3] = v.w;
    }

    float m = l[0]; int mi = lane * 4;
    #pragma unroll
    for (int it = 0; it < 8; ++it)
        #pragma unroll
        for (int j = 0; j < 4; ++j) {
            const int col = it * 128 + lane * 4 + j;
            if (l[it * 4 + j] > m || (l[it * 4 + j] == m && col < mi)) {
                m = l[it * 4 + j]; mi = col;
            }
        }
    #pragma unroll
    for (int o = 16; o > 0; o >>= 1) {
        float ov = __shfl_xor_sync(0xffffffffu, m, o);
        int   oi = __shfl_xor_sync(0xffffffffu, mi, o);
        if (ov > m || (ov == m && oi < mi)) { m = ov; mi = oi; }
    }

    float zs = 0.f;
    #pragma unroll
    for (int i = 0; i < 32; ++i) { l[i] = __expf(l[i] - m); zs += l[i]; }
    #pragma unroll
    for (int o = 16; o > 0; o >>= 1) zs += __shfl_xor_sync(0xffffffffu, zs, o);
    const float invZ = 1.0f / zs;

    float ms = 0.f; int cl = 0;
    #pragma unroll
    for (int i = 0; i < 32; ++i) {
        l[i] *= invZ;
        if (l[i] > 0.1f) { ms += l[i]; ++cl; }
    }
    #pragma unroll
    for (int o = 16; o > 0; o >>= 1) ms += __shfl_xor_sync(0xffffffffu, ms, o);

    int inc = cl;
    #pragma unroll
    for (int o = 1; o < 32; o <<= 1) {
        int n = __shfl_up_sync(0xffffffffu, inc, o);
        if (lane >= o) inc += n;
    }
    const int excl = inc - cl;
    const int total = __shfl_sync(0xffffffffu, inc, 31);

    if (total > 0) {
        const float inv = 1.0f / ms;
        int pos = excl;
        #pragma unroll
        for (int it = 0; it < 8; ++it) {
            float4 o4;
            float q[4];
            #pragma unroll
            for (int j = 0; j < 4; ++j) {
                const float p = l[it * 4 + j];
                const bool sel = p > 0.1f;
                q[j] = sel ? p * inv : 0.f;
                if (sel) {
                    if (pos < NNZ_CAP) {
                        const int col = it * 128 + lane * 4 + j;
                        sidx[(size_t)r * NNZ_CAP + pos] = col;
                        sval[(size_t)r * NNZ_CAP + pos] = q[j];
                    }
                    ++pos;
                }
            }
            o4.x = q[0]; o4.y = q[1]; o4.z = q[2]; o4.w = q[3];
            __stcs((float4*)(Pr + it * 128 + lane * 4), o4);
        }
    } else {
        #pragma unroll
        for (int it = 0; it < 8; ++it) {
            float4 o4;
            #pragma unroll
            for (int j = 0; j < 4; ++j) {
                const int col = it * 128 + lane * 4 + j;
                ((float*)&o4)[j] = (col == mi) ? 1.f : 0.f;
            }
            __stcs((float4*)(Pr + it * 128 + lane * 4), o4);
        }
        if (lane == 0) {
            sidx[(size_t)r * NNZ_CAP] = mi;
            sval[(size_t)r * NNZ_CAP] = 1.0f;
        }
    }
    if (lane == 0) {
        int c = (total > 0) ? total : 1;
        scnt[r] = (c < NNZ_CAP) ? c : NNZ_CAP;
    }
}

// ---------------------------------------------------------------------------
// Sparse AV: one warp per attention row. out[i,:] = sum_k val_k * V[idx_k,:]
// ---------------------------------------------------------------------------
__global__ __launch_bounds__(256) void av_sparse_kernel(
    const int* __restrict__ scnt, const int* __restrict__ sidx,
    const float* __restrict__ sval, const float* __restrict__ qkv,
    float* __restrict__ ao)
{
    const int r = blockIdx.x * 8 + (threadIdx.x >> 5);
    const int lane = threadIdx.x & 31;

    const int bh = r >> 10, i = r & 1023;
    const int b = bh >> 4, h = bh & 15;
    const float* Vb = qkv + (size_t)b * Ss * QKVN + 2 * Ee + h * DH;

    const int c = scnt[r];
    float a0 = 0.f, a1 = 0.f;
    for (int k = 0; k < c; ++k) {
        const int j = sidx[(size_t)r * NNZ_CAP + k];
        const float v = sval[(size_t)r * NNZ_CAP + k];
        const float* Vr = Vb + (size_t)j * QKVN;
        a0 += v * Vr[lane];
        a1 += v * Vr[lane + 32];
    }
    float* Or = ao + (size_t)(b * Ss + i) * Ee + h * DH;
    Or[lane] = a0;
    Or[lane + 32] = a1;
}

// ---------------------------------------------------------------------------
// Launch
// ---------------------------------------------------------------------------
static float* sym_addr(const void* sym)
{
    void* p = nullptr;
    cudaGetSymbolAddress(&p, sym);
    return (float*)p;
}

extern "C" void kernel_launch(void* const* d_in, const int* in_sizes, int n_in,
                              void* d_out, int out_size)
{
    const float* x      = (const float*)d_in[0];
    const float* w_qkv  = (const float*)d_in[1];
    const float* b_qkv  = (const float*)d_in[2];
    const float* w_proj = (const float*)d_in[3];
    const float* b_proj = (const float*)d_in[4];

    float* qkv = sym_addr(g_qkv);
    float* ao  = sym_addr(g_ao);
    int*   scnt = (int*)sym_addr(g_scnt);
    int*   sidx = (int*)sym_addr(g_sidx);
    float* sval = sym_addr(g_sval);

    const size_t OUT_N  = (size_t)Bb * Ss * Ee;
    const size_t ATTN_N = (size_t)Bb * Hh * Ss * Ss;

    float* out = (float*)d_out;
    float* P;
    float* mainOut;
    if ((size_t)out_size >= OUT_N + ATTN_N) {
        mainOut = out;
        P = out + OUT_N;
    } else if ((size_t)out_size == ATTN_N) {
        mainOut = sym_addr(g_spill);
        P = out;
    } else {
        mainOut = out;
        P = sym_addr(g_P);
    }

    const int smemN = G1_SMEM_N * sizeof(float);   // 104448
    const int smemT = G1_SMEM_T * sizeof(float);   // 110592
    cudaFuncSetAttribute(gemm_qkv_kernel,
                         cudaFuncAttributeMaxDynamicSharedMemorySize, smemN);
    cudaFuncSetAttribute(gemm_x1_kernel,
                         cudaFuncAttributeMaxDynamicSharedMemorySize, smemN);
    cudaFuncSetAttribute(gemm_qkt_kernel,
                         cudaFuncAttributeMaxDynamicSharedMemorySize, smemT);

    // 1. merged QKV projection: [4096,1024] @ [1024,3072] + bias
    //    cols < 2048 (Q,K): tf32x3; cols >= 2048 (V): tf32x1
    {
        dim3 grid(QKVN / 128, MROWS / 128, 1);
        gemm_qkv_kernel<<<grid, 128, smemN>>>(
            x, w_qkv, b_qkv, qkv, Ee, Ee, QKVN, QKVN, /*xsplit=*/16);
    }
    // 2. QK^T logits per (b,h), alpha = Dh^-0.5 (tf32x3)
    {
        dim3 grid(Ss / 128, Ss / 128, Bb * Hh);
        gemm_qkt_kernel<<<grid, 128, smemT>>>(qkv, P);
    }
    // 3. warp-per-row softmax + threshold mask + renorm + sparse extraction
    softmax_mask_kernel<<<NROWS / 8, 256>>>(P, scnt, sidx, sval);
    // 4. sparse AV (<= 9 nnz per row guaranteed)
    av_sparse_kernel<<<NROWS / 8, 256>>>(scnt, sidx, sval, qkv, ao);
    // 5. output projection: [4096,1024] @ [1024,1024] + bias (tf32x1)
    {
        dim3 grid(Ee / 128, MROWS / 128, 1);
        gemm_x1_kernel<<<grid, 128, smemN>>>(
            ao, w_proj, b_proj, mainOut, Ee, Ee, Ee, Ee);
    }
}

// round 14
// speedup vs baseline: 1.2190x; 1.0141x over previous
#include <cuda_runtime.h>
#include <math.h>
#include <stdint.h>

// Problem constants
#define Bb 4
#define Ss 1024
#define Ee 1024
#define Hh 16
#define DH 64
#define MROWS (Bb * Ss)      // 4096
#define QKVN (3 * Ee)        // 3072
#define NROWS (Bb * Hh * Ss) // 65536 attention rows
#define NNZ_CAP 16

// Scratch
__device__ float g_qkv[(size_t)MROWS * QKVN];
__device__ float g_P[(size_t)Bb * Hh * Ss * Ss];
__device__ float g_ao[(size_t)MROWS * Ee];
__device__ float g_spill[(size_t)MROWS * Ee];

// ---------------------------------------------------------------------------
// Common helpers
// ---------------------------------------------------------------------------
__device__ __forceinline__ unsigned f2tf32_rna(float x) {
    unsigned u;
    asm("cvt.rna.tf32.f32 %0, %1;" : "=r"(u) : "f"(x));
    return u;
}

template <int PASSES>
__device__ __forceinline__ void splitP(float x, unsigned& h, unsigned& l) {
    if (PASSES == 1) {
        h = f2tf32_rna(x);            // single pass: round-to-nearest tf32
        l = 0u;
    } else {
        unsigned hu = __float_as_uint(x) & 0xffffe000u;  // truncate
        h = hu;
        l = __float_as_uint(x - __uint_as_float(hu));    // residual
    }
}

#define MMA_TF32(cc, aa, bb)                                              \
    asm volatile(                                                          \
        "mma.sync.aligned.m16n8k8.row.col.f32.tf32.tf32.f32 "             \
        "{%0,%1,%2,%3}, {%4,%5,%6,%7}, {%8,%9}, {%0,%1,%2,%3};"           \
        : "+f"(cc[0]), "+f"(cc[1]), "+f"(cc[2]), "+f"(cc[3])              \
        : "r"(aa[0]), "r"(aa[1]), "r"(aa[2]), "r"(aa[3]),                 \
          "r"(bb[0]), "r"(bb[1]))

#define CP_ASYNC16(dst, src)                                              \
    asm volatile("cp.async.cg.shared.global [%0], [%1], 16;"              \
                 :: "r"(dst), "l"(src))
#define CP_COMMIT() asm volatile("cp.async.commit_group;")
#define CP_WAIT_ALL() asm volatile("cp.async.wait_group 0;")
#define CP_WAIT1() asm volatile("cp.async.wait_group 1;")

// ===========================================================================
// G1 mainloop: 128x128 CTA tile, BK=32, 128 threads (2x2 warps, 64x64 tile),
// 3-stage cp.async pipeline. Pass-major MMA order (hh / hl / lh as separate
// mt sweeps) so dependent MMAs on the same acc are 4 issues apart.
// ===========================================================================
#define ASTR 36
#define G1_A_TILE (128 * ASTR)        // 4608 floats
#define G1_BT_TILE (128 * ASTR)       // 4608
#define G1_BN_TILE (32 * 128)         // 4096
#define G1_SMEM_T (3 * (G1_A_TILE + G1_BT_TILE))   // 110592 B
#define G1_SMEM_N (3 * (G1_A_TILE + G1_BN_TILE))   // 104448 B

template <int TRANSB>
__device__ __forceinline__ void g1_load(
    const float* __restrict__ Abase, const float* __restrict__ Bbase,
    int lda, int ldb, int k0, float* As, float* Bs, int tid)
{
    {
        const int row = tid >> 3;
        const int col = (tid & 7) * 4;
        const float* src = Abase + (size_t)row * lda + k0 + col;
        unsigned dst = (unsigned)__cvta_generic_to_shared(As + row * ASTR + col);
        #pragma unroll
        for (int r = 0; r < 8; ++r)
            CP_ASYNC16(dst + r * 16 * ASTR * 4, src + (size_t)r * 16 * lda);
    }
    if (TRANSB) {
        const int row = tid >> 3;
        const int col = (tid & 7) * 4;
        const float* src = Bbase + (size_t)row * ldb + k0 + col;
        unsigned dst = (unsigned)__cvta_generic_to_shared(Bs + row * ASTR + col);
        #pragma unroll
        for (int r = 0; r < 8; ++r)
            CP_ASYNC16(dst + r * 16 * ASTR * 4, src + (size_t)r * 16 * ldb);
    } else {
        #pragma unroll
        for (int r = 0; r < 8; ++r) {
            const int elem = r * 128 + tid;
            const int kr = elem >> 5;
            const int c4 = (elem & 31) * 4;
            const float* src = Bbase + (size_t)(k0 + kr) * ldb + c4;
            unsigned dst = (unsigned)__cvta_generic_to_shared(
                Bs + kr * 128 + (c4 ^ (8 * (kr & 3))));
            CP_ASYNC16(dst, src);
        }
    }
}

template <int TRANSB, int PASSES>
__device__ __forceinline__ void g1_run(
    const float* __restrict__ Abase, const float* __restrict__ Bbase,
    const float* __restrict__ bias, float* __restrict__ Cb,
    int K, int lda, int ldb, int ldc, float alpha,
    float* As, float* Bs, int colBase)
{
    const int B_TILE = TRANSB ? G1_BT_TILE : G1_BN_TILE;
    const int tid = threadIdx.x;
    const int warp = tid >> 5, lane = tid & 31;
    const int wm = warp >> 1, wn = warp & 1;
    const int g = lane >> 2, t = lane & 3;

    float acc[4][8][4];
    #pragma unroll
    for (int mt = 0; mt < 4; ++mt)
        #pragma unroll
        for (int nt = 0; nt < 8; ++nt)
            #pragma unroll
            for (int r = 0; r < 4; ++r) acc[mt][nt][r] = 0.f;

    const int KT = K >> 5;

    g1_load<TRANSB>(Abase, Bbase, lda, ldb, 0, As, Bs, tid);
    CP_COMMIT();
    if (KT > 1) {
        g1_load<TRANSB>(Abase, Bbase, lda, ldb, 32,
                        As + G1_A_TILE, Bs + B_TILE, tid);
        CP_COMMIT();
    }

    for (int kt = 0; kt < KT; ++kt) {
        if (kt < KT - 1) CP_WAIT1(); else CP_WAIT_ALL();
        __syncthreads();

        if (kt + 2 < KT) {
            const int buf = (kt + 2) % 3;
            g1_load<TRANSB>(Abase, Bbase, lda, ldb, (kt + 2) * 32,
                            As + buf * G1_A_TILE, Bs + buf * B_TILE, tid);
            CP_COMMIT();
        }

        const float* Ac = As + (kt % 3) * G1_A_TILE;
        const float* Bc = Bs + (kt % 3) * B_TILE;

        #pragma unroll
        for (int kk = 0; kk < 32; kk += 8) {
            unsigned a_h[4][4], a_l[4][4];
            const int kcol = kk + t;
            #pragma unroll
            for (int mt = 0; mt < 4; ++mt) {
                const int m0 = wm * 64 + mt * 16 + g;
                splitP<PASSES>(Ac[m0 * ASTR + kcol],           a_h[mt][0], a_l[mt][0]);
                splitP<PASSES>(Ac[(m0 + 8) * ASTR + kcol],     a_h[mt][1], a_l[mt][1]);
                splitP<PASSES>(Ac[m0 * ASTR + kcol + 4],       a_h[mt][2], a_l[mt][2]);
                splitP<PASSES>(Ac[(m0 + 8) * ASTR + kcol + 4], a_h[mt][3], a_l[mt][3]);
            }
            #pragma unroll
            for (int nt = 0; nt < 8; ++nt) {
                const int n0 = wn * 64 + nt * 8 + g;
                float y0, y1;
                if (TRANSB) {
                    y0 = Bc[n0 * ASTR + kk + t];
                    y1 = Bc[n0 * ASTR + kk + t + 4];
                } else {
                    const int nsw = n0 ^ (8 * t);
                    y0 = Bc[(kk + t) * 128 + nsw];
                    y1 = Bc[(kk + t + 4) * 128 + nsw];
                }
                unsigned b_h[2], b_l[2];
                splitP<PASSES>(y0, b_h[0], b_l[0]);
                splitP<PASSES>(y1, b_h[1], b_l[1]);
                // pass-major: dependent MMAs on the same acc are 4 apart
                #pragma unroll
                for (int mt = 0; mt < 4; ++mt)
                    MMA_TF32(acc[mt][nt], a_h[mt], b_h);
                if (PASSES >= 2)
                    #pragma unroll
                    for (int mt = 0; mt < 4; ++mt)
                        MMA_TF32(acc[mt][nt], a_h[mt], b_l);
                if (PASSES >= 3)
                    #pragma unroll
                    for (int mt = 0; mt < 4; ++mt)
                        MMA_TF32(acc[mt][nt], a_l[mt], b_h);
            }
        }
    }

    // epilogue
    #pragma unroll
    for (int mt = 0; mt < 4; ++mt) {
        #pragma unroll
        for (int nt = 0; nt < 8; ++nt) {
            const int row0 = blockIdx.y * 128 + wm * 64 + mt * 16 + g;
            const int col  = colBase + wn * 64 + nt * 8 + t * 2;
            float bv0 = 0.f, bv1 = 0.f;
            if (bias) { bv0 = bias[col]; bv1 = bias[col + 1]; }
            float2 v0 = make_float2(acc[mt][nt][0] * alpha + bv0,
                                    acc[mt][nt][1] * alpha + bv1);
            *(float2*)(Cb + (size_t)row0 * ldc + col) = v0;
            float2 v1 = make_float2(acc[mt][nt][2] * alpha + bv0,
                                    acc[mt][nt][3] * alpha + bv1);
            *(float2*)(Cb + (size_t)(row0 + 8) * ldc + col) = v1;
        }
    }
}

// ---------------------------------------------------------------------------
// Merged QKV projection: blockIdx.x < xsplit -> tf32x3 (Q,K), else tf32x1 (V)
// ---------------------------------------------------------------------------
__global__ __launch_bounds__(128) void gemm_qkv_kernel(
    const float* __restrict__ A, const float* __restrict__ B,
    const float* __restrict__ bias, float* __restrict__ C,
    int K, int lda, int ldb, int ldc, int xsplit)
{
    extern __shared__ float sm[];
    float* As = sm;
    float* Bs = sm + 3 * G1_A_TILE;

    const float* Abase = A + (size_t)blockIdx.y * 128 * lda;
    const float* Bbase = B + blockIdx.x * 128;

    if ((int)blockIdx.x < xsplit)
        g1_run<0, 3>(Abase, Bbase, bias, C, K, lda, ldb, ldc, 1.0f,
                     As, Bs, blockIdx.x * 128);
    else
        g1_run<0, 1>(Abase, Bbase, bias, C, K, lda, ldb, ldc, 1.0f,
                     As, Bs, blockIdx.x * 128);
}

// ---------------------------------------------------------------------------
// Plain GEMM (proj): tf32x1
// ---------------------------------------------------------------------------
__global__ __launch_bounds__(128) void gemm_x1_kernel(
    const float* __restrict__ A, const float* __restrict__ B,
    const float* __restrict__ bias, float* __restrict__ C,
    int K, int lda, int ldb, int ldc)
{
    extern __shared__ float sm[];
    float* As = sm;
    float* Bs = sm + 3 * G1_A_TILE;

    const float* Abase = A + (size_t)blockIdx.y * 128 * lda;
    const float* Bbase = B + blockIdx.x * 128;
    g1_run<0, 1>(Abase, Bbase, bias, C, K, lda, ldb, ldc, 1.0f,
                 As, Bs, blockIdx.x * 128);
}

// ---------------------------------------------------------------------------
// QK^T: per (b,h), transB, tf32x3
// ---------------------------------------------------------------------------
__global__ __launch_bounds__(128) void gemm_qkt_kernel(
    const float* __restrict__ qkv, float* __restrict__ P)
{
    extern __shared__ float sm[];
    float* As = sm;
    float* Bs = sm + 3 * G1_A_TILE;

    const int z = blockIdx.z;
    const int b = z >> 4, h = z & 15;
    const float* Ab  = qkv + (size_t)b * Ss * QKVN + h * DH;
    const float* Bbp = qkv + (size_t)b * Ss * QKVN + Ee + h * DH;
    float* Cb = P + (size_t)z * Ss * Ss;

    const float* Abase = Ab + (size_t)blockIdx.y * 128 * QKVN;
    const float* Bbase = Bbp + (size_t)blockIdx.x * 128 * QKVN;

    g1_run<1, 3>(Abase, Bbase, nullptr, Cb, DH, QKVN, QKVN, Ss, 0.125f,
                 As, Bs, blockIdx.x * 128);
}

// ---------------------------------------------------------------------------
// Warp-per-row softmax + threshold mask + renorm + FUSED sparse AV.
// One warp per 1024-col row; nnz staged in per-warp smem, then V gathered
// immediately (<=9 rows) and ao written — no separate AV kernel.
// ---------------------------------------------------------------------------
__global__ __launch_bounds__(256) void softmax_av_kernel(
    float* __restrict__ P, const float* __restrict__ qkv,
    float* __restrict__ ao)
{
    __shared__ int   s_i[8][NNZ_CAP];
    __shared__ float s_v[8][NNZ_CAP];

    const int w = threadIdx.x >> 5;
    const int r = blockIdx.x * 8 + w;
    const int lane = threadIdx.x & 31;
    float* Pr = P + (size_t)r * Ss;

    float l[32];
    #pragma unroll
    for (int it = 0; it < 8; ++it) {
        float4 v = __ldcs((const float4*)(Pr + it * 128 + lane * 4));
        l[it * 4 + 0] = v.x; l[it * 4 + 1] = v.y;
        l[it * 4 + 2] = v.z; l[it * 4 + 3] = v.w;
    }

    // ---- max + argmax (first occurrence) ----
    float m = l[0]; int mi = lane * 4;
    #pragma unroll
    for (int it = 0; it < 8; ++it)
        #pragma unroll
        for (int j = 0; j < 4; ++j) {
            const int col = it * 128 + lane * 4 + j;
            if (l[it * 4 + j] > m || (l[it * 4 + j] == m && col < mi)) {
                m = l[it * 4 + j]; mi = col;
            }
        }
    #pragma unroll
    for (int o = 16; o > 0; o >>= 1) {
        float ov = __shfl_xor_sync(0xffffffffu, m, o);
        int   oi = __shfl_xor_sync(0xffffffffu, mi, o);
        if (ov > m || (ov == m && oi < mi)) { m = ov; mi = oi; }
    }

    // ---- exp + Z ----
    float zs = 0.f;
    #pragma unroll
    for (int i = 0; i < 32; ++i) { l[i] = __expf(l[i] - m); zs += l[i]; }
    #pragma unroll
    for (int o = 16; o > 0; o >>= 1) zs += __shfl_xor_sync(0xffffffffu, zs, o);
    const float invZ = 1.0f / zs;

    // ---- p, masked sum, local count ----
    float ms = 0.f; int cl = 0;
    #pragma unroll
    for (int i = 0; i < 32; ++i) {
        l[i] *= invZ;
        if (l[i] > 0.1f) { ms += l[i]; ++cl; }
    }
    #pragma unroll
    for (int o = 16; o > 0; o >>= 1) ms += __shfl_xor_sync(0xffffffffu, ms, o);

    // ---- warp exclusive prefix scan ----
    int inc = cl;
    #pragma unroll
    for (int o = 1; o < 32; o <<= 1) {
        int n = __shfl_up_sync(0xffffffffu, inc, o);
        if (lane >= o) inc += n;
    }
    const int excl = inc - cl;
    const int total = __shfl_sync(0xffffffffu, inc, 31);

    if (total > 0) {
        const float inv = 1.0f / ms;
        int pos = excl;
        #pragma unroll
        for (int it = 0; it < 8; ++it) {
            float4 o4;
            float q[4];
            #pragma unroll
            for (int j = 0; j < 4; ++j) {
                const float p = l[it * 4 + j];
                const bool sel = p > 0.1f;
                q[j] = sel ? p * inv : 0.f;
                if (sel) {
                    if (pos < NNZ_CAP) {
                        s_i[w][pos] = it * 128 + lane * 4 + j;
                        s_v[w][pos] = q[j];
                    }
                    ++pos;
                }
            }
            o4.x = q[0]; o4.y = q[1]; o4.z = q[2]; o4.w = q[3];
            __stcs((float4*)(Pr + it * 128 + lane * 4), o4);
        }
    } else {
        #pragma unroll
        for (int it = 0; it < 8; ++it) {
            float4 o4;
            #pragma unroll
            for (int j = 0; j < 4; ++j) {
                const int col = it * 128 + lane * 4 + j;
                ((float*)&o4)[j] = (col == mi) ? 1.f : 0.f;
            }
            __stcs((float4*)(Pr + it * 128 + lane * 4), o4);
        }
        if (lane == 0) {
            s_i[w][0] = mi;
            s_v[w][0] = 1.0f;
        }
    }
    __syncwarp();

    // ---- fused sparse AV: out[i,:] = sum_k val_k * V[idx_k,:] ----
    const int cnt0 = (total > 0) ? total : 1;
    const int cnt = (cnt0 < NNZ_CAP) ? cnt0 : NNZ_CAP;

    const int bh = r >> 10, i = r & 1023;
    const int b = bh >> 4, h = bh & 15;
    const float* Vb = qkv + (size_t)b * Ss * QKVN + 2 * Ee + h * DH;

    float a0 = 0.f, a1 = 0.f;
    for (int k = 0; k < cnt; ++k) {
        const int j = s_i[w][k];
        const float v = s_v[w][k];
        const float* Vr = Vb + (size_t)j * QKVN;
        a0 += v * Vr[lane];
        a1 += v * Vr[lane + 32];
    }
    float* Or = ao + (size_t)(b * Ss + i) * Ee + h * DH;
    Or[lane] = a0;
    Or[lane + 32] = a1;
}

// ---------------------------------------------------------------------------
// Launch
// ---------------------------------------------------------------------------
static float* sym_addr(const void* sym)
{
    void* p = nullptr;
    cudaGetSymbolAddress(&p, sym);
    return (float*)p;
}

extern "C" void kernel_launch(void* const* d_in, const int* in_sizes, int n_in,
                              void* d_out, int out_size)
{
    const float* x      = (const float*)d_in[0];
    const float* w_qkv  = (const float*)d_in[1];
    const float* b_qkv  = (const float*)d_in[2];
    const float* w_proj = (const float*)d_in[3];
    const float* b_proj = (const float*)d_in[4];

    float* qkv = sym_addr(g_qkv);
    float* ao  = sym_addr(g_ao);

    const size_t OUT_N  = (size_t)Bb * Ss * Ee;
    const size_t ATTN_N = (size_t)Bb * Hh * Ss * Ss;

    float* out = (float*)d_out;
    float* P;
    float* mainOut;
    if ((size_t)out_size >= OUT_N + ATTN_N) {
        mainOut = out;
        P = out + OUT_N;
    } else if ((size_t)out_size == ATTN_N) {
        mainOut = sym_addr(g_spill);
        P = out;
    } else {
        mainOut = out;
        P = sym_addr(g_P);
    }

    const int smemN = G1_SMEM_N * sizeof(float);   // 104448
    const int smemT = G1_SMEM_T * sizeof(float);   // 110592
    cudaFuncSetAttribute(gemm_qkv_kernel,
                         cudaFuncAttributeMaxDynamicSharedMemorySize, smemN);
    cudaFuncSetAttribute(gemm_x1_kernel,
                         cudaFuncAttributeMaxDynamicSharedMemorySize, smemN);
    cudaFuncSetAttribute(gemm_qkt_kernel,
                         cudaFuncAttributeMaxDynamicSharedMemorySize, smemT);

    // 1. merged QKV projection: [4096,1024] @ [1024,3072] + bias
    //    cols < 2048 (Q,K): tf32x3; cols >= 2048 (V): tf32x1
    {
        dim3 grid(QKVN / 128, MROWS / 128, 1);
        gemm_qkv_kernel<<<grid, 128, smemN>>>(
            x, w_qkv, b_qkv, qkv, Ee, Ee, QKVN, QKVN, /*xsplit=*/16);
    }
    // 2. QK^T logits per (b,h), alpha = Dh^-0.5 (tf32x3)
    {
        dim3 grid(Ss / 128, Ss / 128, Bb * Hh);
        gemm_qkt_kernel<<<grid, 128, smemT>>>(qkv, P);
    }
    // 3. warp-per-row softmax + mask + renorm + fused sparse AV
    softmax_av_kernel<<<NROWS / 8, 256>>>(P, qkv, ao);
    // 4. output projection: [4096,1024] @ [1024,1024] + bias (tf32x1)
    {
        dim3 grid(Ee / 128, MROWS / 128, 1);
        gemm_x1_kernel<<<grid, 128, smemN>>>(
            ao, w_proj, b_proj, mainOut, Ee, Ee, Ee, Ee);
    }
}